// round 12
// baseline (speedup 1.0000x reference)
#include <cuda_runtime.h>
#include <cuda_fp16.h>
#include <cstdint>

#define NMAX 50000
#define EMAX 800000
#define GNUM 512
#define HID 64
#define LAY 5
#define HL 320
#define BN_EPS 1e-5f
#define PB 592
#define NT 512
#define NSLICE 16
#define STATSZ (LAY * 256)

// ---------------- static scratch ----------------
__device__ float  g_z[(size_t)NMAX * HID];      // post-GEMM1 pre-BN z, fp32
__device__ __half g_h16[(size_t)NMAX * HL];     // RAW gemm2 outputs (pre-BN), fp16
__device__ float  g_statp[NSLICE * STATSZ];
__device__ int    g_deg[NMAX];
__device__ int    g_rowptr[NMAX + 1];
__device__ int    g_cur[NMAX];
__device__ int    g_part[256];
__device__ int    g_partscan[256];
__device__ int    g_csrc[EMAX];
__device__ int    g_is64_e, g_is64_b;
__device__ unsigned g_count = 0, g_epoch = 0;

__device__ __forceinline__ long ldidx(const void* p, long i, int is64) {
    return is64 ? (long)((const long long*)p)[i] : (long)((const int*)p)[i];
}

__device__ __forceinline__ unsigned ld_epoch() {
    unsigned v;
    asm volatile("ld.global.cg.u32 %0, [%1];" : "=r"(v) : "l"(&g_epoch) : "memory");
    return v;
}

__device__ __forceinline__ void gbar() {
    __syncthreads();
    if (threadIdx.x == 0) {
        __threadfence();
        unsigned e = ld_epoch();
        if (atomicAdd(&g_count, 1) == gridDim.x - 1) {
            atomicExch(&g_count, 0u);
            __threadfence();
            atomicExch(&g_epoch, e + 1);
        } else {
            unsigned cur;
            do { __nanosleep(20); cur = ld_epoch(); } while (cur == e);
        }
        __threadfence();
    }
    __syncthreads();
}

// ---------------- shared memory ----------------
struct SmGemm {
    float w[64][64];
    float in[64][65];
    float a[64];
    float b[64];
    float bias[64];
    float st[128];
};
struct SmPool { float a[HL]; float b[HL]; };
struct SmScan { int sh[NT + 1]; };
struct SmL0   { float xr[64]; float st[128]; };
union __align__(16) SmU {
    SmGemm g; SmPool p; SmScan s; SmL0 l0;
};

__global__ void __launch_bounds__(NT, 4) fused_all(
    const float* __restrict__ x, const void* __restrict__ ei,
    const void* __restrict__ batch,
    const float* __restrict__ w1_0, const float* __restrict__ w1_rest,
    const float* __restrict__ b1,
    const float* __restrict__ gm, const float* __restrict__ bm,
    const float* __restrict__ w2, const float* __restrict__ b2,
    const float* __restrict__ go, const float* __restrict__ bo,
    const float* __restrict__ lin_w, const float* __restrict__ lin_b,
    float* __restrict__ out, int n, int E, int bcount, float invN)
{
    __shared__ SmU sm;
    int t = threadIdx.x, b = blockIdx.x, nb = gridDim.x;
    int lane = t & 31, warp = t >> 5;
    long gstride = (long)nb * NT;
    int slice = (b & (NSLICE - 1)) * STATSZ;

    // ---------- P0: zero + detect ----------
    for (long i = (long)b * NT + t; i < n; i += gstride) g_deg[i] = 0;
    for (long i = (long)b * NT + t; i < NSLICE * STATSZ; i += gstride) g_statp[i] = 0.f;
    if (b == 1) {
        const int* p = (const int*)ei;
        int f = 0;
        for (int i = t; i < 4096; i += NT) if (p[2 * i + 1] != 0) f = 1;
        f = __syncthreads_or(f);
        if (t == 0) g_is64_e = (f == 0);
        const int* q = (const int*)batch;
        int hf = bcount / 2;
        int f2 = 0;
        for (int i = t; i < 2048; i += NT) {
            int pos = hf - 1 - i;
            if (pos >= 0 && q[2 * pos + 1] != 0) f2 = 1;
        }
        f2 = __syncthreads_or(f2);
        if (t == 0) g_is64_b = (f2 == 0);
    }
    gbar();

    // ---------- P1: degree histogram ----------
    {
        int is64 = g_is64_e;
        for (long e0 = (long)b * NT + t; e0 < E; e0 += gstride) {
            int dst = (int)ldidx(ei, (long)E + e0, is64);
            atomicAdd(&g_deg[dst], 1);
        }
    }
    gbar();

    int nch = (n + NT - 1) / NT;

    // ---------- P2: chunk sums ----------
    for (int c = b; c < nch; c += nb) {
        int i = c * NT + t;
        sm.s.sh[t] = (i < n) ? g_deg[i] : 0;
        __syncthreads();
        for (int off = NT / 2; off > 0; off >>= 1) {
            if (t < off) sm.s.sh[t] += sm.s.sh[t + off];
            __syncthreads();
        }
        if (t == 0) g_part[c] = sm.s.sh[0];
        __syncthreads();
    }
    gbar();

    // ---------- P3: scan of chunk sums ----------
    if (b == 0) {
        int v = (t < nch) ? g_part[t] : 0;
        sm.s.sh[t] = v;
        __syncthreads();
        for (int off = 1; off < NT; off <<= 1) {
            int xv = (t >= off) ? sm.s.sh[t - off] : 0;
            __syncthreads();
            sm.s.sh[t] += xv;
            __syncthreads();
        }
        if (t < nch) g_partscan[t] = sm.s.sh[t] - v;
    }
    gbar();

    // ---------- P4: rowptr ----------
    for (int c = b; c < nch; c += nb) {
        int i = c * NT + t;
        int v = (i < n) ? g_deg[i] : 0;
        sm.s.sh[t] = v;
        __syncthreads();
        for (int off = 1; off < NT; off <<= 1) {
            int xv = (t >= off) ? sm.s.sh[t - off] : 0;
            __syncthreads();
            sm.s.sh[t] += xv;
            __syncthreads();
        }
        if (i < n) {
            int rp = g_partscan[c] + sm.s.sh[t] - v;
            g_rowptr[i] = rp;
            g_cur[i] = rp;
            if (i == n - 1) g_rowptr[n] = E;
        }
        __syncthreads();
    }
    gbar();

    // ---------- P5: fill CSR ----------
    {
        int is64 = g_is64_e;
        for (long e0 = (long)b * NT + t; e0 < E; e0 += gstride) {
            int src = (int)ldidx(ei, e0, is64);
            int dst = (int)ldidx(ei, (long)E + e0, is64);
            int pos = atomicAdd(&g_cur[dst], 1);
            g_csrc[pos] = src;
        }
    }
    gbar();

    int ntiles = (n + 63) / 64;

    // ---------- P6: layer-0 ----------
    for (int i = t; i < 128; i += NT) sm.l0.st[i] = 0.f;
    __syncthreads();
    for (int tile = b; tile < ntiles; tile += nb) {
        int r0 = tile * 64;
        for (int rr = 0; rr < 4; rr++) {
            int rl = warp * 4 + rr;
            int row = r0 + rl;
            float acc = 0.f;
            if (row < n) {
                int beg = g_rowptr[row], end = g_rowptr[row + 1];
                for (int j = beg + lane; j < end; j += 32)
                    acc += x[g_csrc[j]];
            }
            #pragma unroll
            for (int o = 16; o > 0; o >>= 1)
                acc += __shfl_xor_sync(0xFFFFFFFFu, acc, o);
            if (lane == 0)
                sm.l0.xr[rl] = (row < n) ? (acc + x[row]) : 0.f;
        }
        __syncthreads();
        int c = t & 63, g4 = t >> 6;
        float wc = w1_0[c], bc = b1[c];
        float s = 0.f, q = 0.f;
        #pragma unroll
        for (int i = 0; i < 8; i++) {
            int row = r0 + g4 * 8 + i;
            if (row < n) {
                float zv = sm.l0.xr[g4 * 8 + i] * wc + bc;
                g_z[(size_t)row * HID + c] = zv;
                s += zv; q += zv * zv;
            }
        }
        atomicAdd(&sm.l0.st[c], s);
        atomicAdd(&sm.l0.st[64 + c], q);
        __syncthreads();
    }
    if (t < 128) atomicAdd(&g_statp[slice + t], sm.l0.st[t]);
    gbar();

    // ---------- layers ----------
    for (int l = 0; l < LAY; l++) {
        // ----- gemm1 + half-split uint2 gather (l >= 1) -----
        if (l > 0) {
            int pc = (l - 1) * HID;
            int pso = (l - 1) * 256 + 128;
            if (t < 64) {
                float s1 = 0.f, s2 = 0.f;
                #pragma unroll 4
                for (int sl = 0; sl < NSLICE; sl++) {
                    const float* sp = g_statp + sl * STATSZ + pso;
                    s1 += __ldcg(sp + t);
                    s2 += __ldcg(sp + 64 + t);
                }
                float mean = s1 * invN;
                float var  = s2 * invN - mean * mean;
                float a = go[pc + t] * rsqrtf(var + BN_EPS);
                sm.g.a[t] = a;
                sm.g.b[t] = bo[pc + t] - mean * a;
                sm.g.bias[t] = b1[l * HID + t];
            }
            const float* w = w1_rest + (size_t)(l - 1) * 4096;
            for (int idx = t; idx < 4096; idx += NT)
                sm.g.w[idx >> 6][idx & 63] = w[idx];
            for (int i = t; i < 128; i += NT) sm.g.st[i] = 0.f;
            __syncthreads();

            int half = lane >> 4, c4 = lane & 15;
            float4 ca = *(const float4*)&sm.g.a[c4 * 4];
            float4 cb = *(const float4*)&sm.g.b[c4 * 4];
            const __half* hbase = g_h16 + pc + c4 * 4;
            int so = l * 256;

            for (int tile = b; tile < ntiles; tile += nb) {
                int r0 = tile * 64;
                for (int rr = 0; rr < 4; rr++) {
                    int rl = warp * 4 + rr;
                    int row = r0 + rl;
                    float4 A = make_float4(0.f, 0.f, 0.f, 0.f);
                    auto accum = [&](uint2 raw) {
                        float2 f01 = __half22float2(*(__half2*)&raw.x);
                        float2 f23 = __half22float2(*(__half2*)&raw.y);
                        A.x += fmaxf(fmaf(f01.x, ca.x, cb.x), 0.f);
                        A.y += fmaxf(fmaf(f01.y, ca.y, cb.y), 0.f);
                        A.z += fmaxf(fmaf(f23.x, ca.z, cb.z), 0.f);
                        A.w += fmaxf(fmaf(f23.y, ca.w, cb.w), 0.f);
                    };
                    if (row < n) {
                        int beg = g_rowptr[row], end = g_rowptr[row + 1];
                        int j = beg + half;
                        while (j + 2 < end) {
                            int s0 = g_csrc[j];
                            int s1 = g_csrc[j + 2];
                            uint2 w0 = *(const uint2*)(hbase + (size_t)s0 * HL);
                            uint2 w1 = *(const uint2*)(hbase + (size_t)s1 * HL);
                            accum(w0);
                            accum(w1);
                            j += 4;
                        }
                        if (j < end) {
                            int s0 = g_csrc[j];
                            uint2 w0 = *(const uint2*)(hbase + (size_t)s0 * HL);
                            accum(w0);
                        }
                    }
                    A.x += __shfl_xor_sync(0xFFFFFFFFu, A.x, 16);
                    A.y += __shfl_xor_sync(0xFFFFFFFFu, A.y, 16);
                    A.z += __shfl_xor_sync(0xFFFFFFFFu, A.z, 16);
                    A.w += __shfl_xor_sync(0xFFFFFFFFu, A.w, 16);
                    if (half == 0) {
                        if (row < n) {
                            uint2 raw = *(const uint2*)(hbase + (size_t)row * HL);
                            accum(raw);
                        }
                        float* ip = &sm.g.in[rl][c4 * 4];
                        ip[0] = A.x; ip[1] = A.y; ip[2] = A.z; ip[3] = A.w;
                    }
                }
                __syncthreads();
                // GEMM: 512 threads, 8 outputs each
                int r = t & 63, c0 = (t >> 6) * 8;
                float acc[8];
                #pragma unroll
                for (int j = 0; j < 8; j++) acc[j] = sm.g.bias[c0 + j];
                #pragma unroll
                for (int k = 0; k < 64; k++) {
                    float a = sm.g.in[r][k];
                    float4 wv0 = *(const float4*)&sm.g.w[k][c0];
                    float4 wv1 = *(const float4*)&sm.g.w[k][c0 + 4];
                    acc[0] = fmaf(a, wv0.x, acc[0]);
                    acc[1] = fmaf(a, wv0.y, acc[1]);
                    acc[2] = fmaf(a, wv0.z, acc[2]);
                    acc[3] = fmaf(a, wv0.w, acc[3]);
                    acc[4] = fmaf(a, wv1.x, acc[4]);
                    acc[5] = fmaf(a, wv1.y, acc[5]);
                    acc[6] = fmaf(a, wv1.z, acc[6]);
                    acc[7] = fmaf(a, wv1.w, acc[7]);
                }
                int gr = r0 + r;
                bool valid = gr < n;
                if (valid) {
                    float4* op = (float4*)&g_z[(size_t)gr * HID + c0];
                    op[0] = make_float4(acc[0], acc[1], acc[2], acc[3]);
                    op[1] = make_float4(acc[4], acc[5], acc[6], acc[7]);
                }
                #pragma unroll
                for (int j = 0; j < 8; j++) {
                    float s = valid ? acc[j] : 0.f;
                    float q = s * s;
                    #pragma unroll
                    for (int o = 16; o > 0; o >>= 1) {
                        s += __shfl_down_sync(0xFFFFFFFFu, s, o);
                        q += __shfl_down_sync(0xFFFFFFFFu, q, o);
                    }
                    if (lane == 0) {
                        atomicAdd(&sm.g.st[c0 + j], s);
                        atomicAdd(&sm.g.st[64 + c0 + j], q);
                    }
                }
                __syncthreads();
            }
            if (t < 128) atomicAdd(&g_statp[slice + so + t], sm.g.st[t]);
            gbar();
        }

        // ----- gemm2: fp32 z in, fp16 h out -----
        {
            int zso = l * 256;
            if (t < 64) {
                float s1 = 0.f, s2 = 0.f;
                #pragma unroll 4
                for (int sl = 0; sl < NSLICE; sl++) {
                    const float* sp = g_statp + sl * STATSZ + zso;
                    s1 += __ldcg(sp + t);
                    s2 += __ldcg(sp + 64 + t);
                }
                float mean = s1 * invN;
                float var  = s2 * invN - mean * mean;
                float a = gm[l * HID + t] * rsqrtf(var + BN_EPS);
                sm.g.a[t] = a;
                sm.g.b[t] = bm[l * HID + t] - mean * a;
                sm.g.bias[t] = b2[l * HID + t];
            }
            const float* w = w2 + (size_t)l * 4096;
            for (int idx = t; idx < 4096; idx += NT)
                sm.g.w[idx >> 6][idx & 63] = w[idx];
            for (int i = t; i < 128; i += NT) sm.g.st[i] = 0.f;
            __syncthreads();

            int vso = l * 256 + 128;

            for (int tile = b; tile < ntiles; tile += nb) {
                int r0 = tile * 64;
                for (int idx = t; idx < 1024; idx += NT) {
                    int r = idx >> 4, k4 = idx & 15;
                    int gr = r0 + r;
                    float4 val = make_float4(0.f, 0.f, 0.f, 0.f);
                    if (gr < n) {
                        float4 z = *(const float4*)(g_z + (size_t)gr * HID + k4 * 4);
                        val.x = fmaxf(fmaf(z.x, sm.g.a[k4*4+0], sm.g.b[k4*4+0]), 0.f);
                        val.y = fmaxf(fmaf(z.y, sm.g.a[k4*4+1], sm.g.b[k4*4+1]), 0.f);
                        val.z = fmaxf(fmaf(z.z, sm.g.a[k4*4+2], sm.g.b[k4*4+2]), 0.f);
                        val.w = fmaxf(fmaf(z.w, sm.g.a[k4*4+3], sm.g.b[k4*4+3]), 0.f);
                    }
                    sm.g.in[r][k4*4+0] = val.x;
                    sm.g.in[r][k4*4+1] = val.y;
                    sm.g.in[r][k4*4+2] = val.z;
                    sm.g.in[r][k4*4+3] = val.w;
                }
                __syncthreads();
                int r = t & 63, c0 = (t >> 6) * 8;
                float acc[8];
                #pragma unroll
                for (int j = 0; j < 8; j++) acc[j] = sm.g.bias[c0 + j];
                #pragma unroll
                for (int k = 0; k < 64; k++) {
                    float a = sm.g.in[r][k];
                    float4 wv0 = *(const float4*)&sm.g.w[k][c0];
                    float4 wv1 = *(const float4*)&sm.g.w[k][c0 + 4];
                    acc[0] = fmaf(a, wv0.x, acc[0]);
                    acc[1] = fmaf(a, wv0.y, acc[1]);
                    acc[2] = fmaf(a, wv0.z, acc[2]);
                    acc[3] = fmaf(a, wv0.w, acc[3]);
                    acc[4] = fmaf(a, wv1.x, acc[4]);
                    acc[5] = fmaf(a, wv1.y, acc[5]);
                    acc[6] = fmaf(a, wv1.z, acc[6]);
                    acc[7] = fmaf(a, wv1.w, acc[7]);
                }
                int gr = r0 + r;
                bool valid = gr < n;
                if (valid) {
                    uint4 pk;
                    __half2* ph = (__half2*)&pk;
                    ph[0] = __float22half2_rn(make_float2(acc[0], acc[1]));
                    ph[1] = __float22half2_rn(make_float2(acc[2], acc[3]));
                    ph[2] = __float22half2_rn(make_float2(acc[4], acc[5]));
                    ph[3] = __float22half2_rn(make_float2(acc[6], acc[7]));
                    *(uint4*)(g_h16 + (size_t)gr * HL + l * HID + c0) = pk;
                }
                #pragma unroll
                for (int j = 0; j < 8; j++) {
                    float s = valid ? acc[j] : 0.f;
                    float q = s * s;
                    #pragma unroll
                    for (int o = 16; o > 0; o >>= 1) {
                        s += __shfl_down_sync(0xFFFFFFFFu, s, o);
                        q += __shfl_down_sync(0xFFFFFFFFu, q, o);
                    }
                    if (lane == 0) {
                        atomicAdd(&sm.g.st[c0 + j], s);
                        atomicAdd(&sm.g.st[64 + c0 + j], q);
                    }
                }
                __syncthreads();
            }
            if (t < 128) atomicAdd(&g_statp[slice + vso + t], sm.g.st[t]);
            gbar();
        }
    }

    // ---------- pool + classifier ----------
    for (int c = t; c < HL; c += NT) {
        int l = c >> 6, ch = c & 63;
        int vso = l * 256 + 128;
        float s1 = 0.f, s2 = 0.f;
        for (int sl = 0; sl < NSLICE; sl++) {
            const float* sp = g_statp + sl * STATSZ + vso;
            s1 += __ldcg(sp + ch);
            s2 += __ldcg(sp + 64 + ch);
        }
        float mean = s1 * invN;
        float var  = s2 * invN - mean * mean;
        float a = go[c] * rsqrtf(var + BN_EPS);
        sm.p.a[c] = a;
        sm.p.b[c] = bo[c] - mean * a;
    }
    __syncthreads();
    {
        int is64 = g_is64_b;
        int warpsTotal = nb * 16;
        int gw = b * 16 + warp;
        for (int g = gw; g < GNUM; g += warpsTotal) {
            int se = n;
            if (lane < 2) {
                int key = g + lane;
                int lo = 0, hi = n;
                while (lo < hi) {
                    int mid = (lo + hi) >> 1;
                    if ((int)ldidx(batch, mid, is64) < key) lo = mid + 1;
                    else hi = mid;
                }
                se = lo;
            }
            int s0 = __shfl_sync(0xFFFFFFFFu, se, 0);
            int e0 = __shfl_sync(0xFFFFFFFFu, se, 1);
            float acc0[5], acc1[5];
            #pragma unroll
            for (int k = 0; k < 5; k++) { acc0[k] = 0.f; acc1[k] = 0.f; }
            float xsum = 0.f;
            int cbase = lane * 2;
            for (int r = s0; r < e0; r++) {
                xsum += x[r];
                const __half2* rp = (const __half2*)(g_h16 + (size_t)r * HL);
                #pragma unroll
                for (int k = 0; k < 5; k++) {
                    float2 f = __half22float2(rp[k * 32 + lane]);
                    int c = k * 64 + cbase;
                    acc0[k] += fmaxf(fmaf(f.x, sm.p.a[c], sm.p.b[c]), 0.f);
                    acc1[k] += fmaxf(fmaf(f.y, sm.p.a[c + 1], sm.p.b[c + 1]), 0.f);
                }
            }
            float o0 = 0.f, o1 = 0.f;
            #pragma unroll
            for (int k = 0; k < 5; k++) {
                int c = k * 64 + cbase;
                o0 = fmaf(acc0[k], lin_w[(1 + c) * 2 + 0], o0);
                o1 = fmaf(acc0[k], lin_w[(1 + c) * 2 + 1], o1);
                o0 = fmaf(acc1[k], lin_w[(2 + c) * 2 + 0], o0);
                o1 = fmaf(acc1[k], lin_w[(2 + c) * 2 + 1], o1);
            }
            #pragma unroll
            for (int o = 16; o > 0; o >>= 1) {
                o0 += __shfl_down_sync(0xFFFFFFFFu, o0, o);
                o1 += __shfl_down_sync(0xFFFFFFFFu, o1, o);
            }
            if (lane == 0) {
                out[g * 2 + 0] = o0 + xsum * lin_w[0] + lin_b[0];
                out[g * 2 + 1] = o1 + xsum * lin_w[1] + lin_b[1];
            }
        }
    }
}

// ---------------- launch ----------------
extern "C" void kernel_launch(void* const* d_in, const int* in_sizes, int n_in,
                              void* d_out, int out_size)
{
    const float* x      = (const float*)d_in[0];
    const void*  ei     = d_in[1];
    const void*  batch  = d_in[2];
    const float* w1_0   = (const float*)d_in[3];
    const float* w1_rest= (const float*)d_in[4];
    const float* b1     = (const float*)d_in[5];
    const float* gm     = (const float*)d_in[6];
    const float* bm     = (const float*)d_in[7];
    const float* w2     = (const float*)d_in[8];
    const float* b2     = (const float*)d_in[9];
    const float* go     = (const float*)d_in[10];
    const float* bo     = (const float*)d_in[11];
    const float* lin_w  = (const float*)d_in[12];
    const float* lin_b  = (const float*)d_in[13];
    float* out = (float*)d_out;

    int N = in_sizes[0];
    int E = in_sizes[1] / 2;
    float invN = 1.f / (float)N;

    fused_all<<<PB, NT>>>(x, ei, batch, w1_0, w1_rest, b1, gm, bm,
                          w2, b2, go, bo, lin_w, lin_b, out,
                          N, E, in_sizes[2], invN);
}

// round 13
// speedup vs baseline: 1.0759x; 1.0759x over previous
#include <cuda_runtime.h>
#include <cuda_fp16.h>
#include <cstdint>

#define NMAX 50000
#define EMAX 800000
#define GNUM 512
#define HID 64
#define LAY 5
#define HL 320
#define BN_EPS 1e-5f
#define PB 444
#define NT 512
#define NSLICE 16
#define STATSZ (LAY * 256)

// ---------------- static scratch ----------------
__device__ float  g_z[(size_t)NMAX * HID];      // post-GEMM1 pre-BN z, fp32
__device__ __half g_h16[(size_t)NMAX * HL];     // RAW gemm2 outputs (pre-BN), fp16
__device__ float  g_statp[NSLICE * STATSZ];
__device__ int    g_deg[NMAX];
__device__ int    g_rowptr[NMAX + 1];
__device__ int    g_cur[NMAX];
__device__ int    g_part[256];
__device__ int    g_partscan[256];
__device__ int    g_csrc[EMAX + 8];             // +8 pad: prefetch reads past row end
__device__ int    g_is64_e, g_is64_b;
__device__ unsigned g_count = 0, g_epoch = 0;

__device__ __forceinline__ long ldidx(const void* p, long i, int is64) {
    return is64 ? (long)((const long long*)p)[i] : (long)((const int*)p)[i];
}

__device__ __forceinline__ unsigned ld_epoch() {
    unsigned v;
    asm volatile("ld.global.cg.u32 %0, [%1];" : "=r"(v) : "l"(&g_epoch) : "memory");
    return v;
}

__device__ __forceinline__ void gbar() {
    __syncthreads();
    if (threadIdx.x == 0) {
        __threadfence();
        unsigned e = ld_epoch();
        if (atomicAdd(&g_count, 1) == gridDim.x - 1) {
            atomicExch(&g_count, 0u);
            __threadfence();
            atomicExch(&g_epoch, e + 1);
        } else {
            unsigned cur;
            do { __nanosleep(20); cur = ld_epoch(); } while (cur == e);
        }
        __threadfence();
    }
    __syncthreads();
}

// ---------------- shared memory ----------------
struct SmGemm {
    float w[64][64];
    float in[64][65];
    float a[64];
    float b[64];
    float bias[64];
    float st[128];
};
struct SmPool { float a[HL]; float b[HL]; };
struct SmScan { int sh[NT + 1]; };
struct SmL0   { float xr[64]; float st[128]; };
union __align__(16) SmU {
    SmGemm g; SmPool p; SmScan s; SmL0 l0;
};

__global__ void __launch_bounds__(NT, 3) fused_all(
    const float* __restrict__ x, const void* __restrict__ ei,
    const void* __restrict__ batch,
    const float* __restrict__ w1_0, const float* __restrict__ w1_rest,
    const float* __restrict__ b1,
    const float* __restrict__ gm, const float* __restrict__ bm,
    const float* __restrict__ w2, const float* __restrict__ b2,
    const float* __restrict__ go, const float* __restrict__ bo,
    const float* __restrict__ lin_w, const float* __restrict__ lin_b,
    float* __restrict__ out, int n, int E, int bcount, float invN)
{
    __shared__ SmU sm;
    int t = threadIdx.x, b = blockIdx.x, nb = gridDim.x;
    int lane = t & 31, warp = t >> 5;
    long gstride = (long)nb * NT;
    int slice = (b & (NSLICE - 1)) * STATSZ;

    // ---------- P0: zero + detect ----------
    for (long i = (long)b * NT + t; i < n; i += gstride) g_deg[i] = 0;
    for (long i = (long)b * NT + t; i < NSLICE * STATSZ; i += gstride) g_statp[i] = 0.f;
    if (b == 1) {
        const int* p = (const int*)ei;
        int f = 0;
        for (int i = t; i < 4096; i += NT) if (p[2 * i + 1] != 0) f = 1;
        f = __syncthreads_or(f);
        if (t == 0) g_is64_e = (f == 0);
        const int* q = (const int*)batch;
        int hf = bcount / 2;
        int f2 = 0;
        for (int i = t; i < 2048; i += NT) {
            int pos = hf - 1 - i;
            if (pos >= 0 && q[2 * pos + 1] != 0) f2 = 1;
        }
        f2 = __syncthreads_or(f2);
        if (t == 0) g_is64_b = (f2 == 0);
    }
    gbar();

    // ---------- P1: degree histogram ----------
    {
        int is64 = g_is64_e;
        for (long e0 = (long)b * NT + t; e0 < E; e0 += gstride) {
            int dst = (int)ldidx(ei, (long)E + e0, is64);
            atomicAdd(&g_deg[dst], 1);
        }
    }
    gbar();

    int nch = (n + NT - 1) / NT;

    // ---------- P2: chunk sums ----------
    for (int c = b; c < nch; c += nb) {
        int i = c * NT + t;
        sm.s.sh[t] = (i < n) ? g_deg[i] : 0;
        __syncthreads();
        for (int off = NT / 2; off > 0; off >>= 1) {
            if (t < off) sm.s.sh[t] += sm.s.sh[t + off];
            __syncthreads();
        }
        if (t == 0) g_part[c] = sm.s.sh[0];
        __syncthreads();
    }
    gbar();

    // ---------- P3: scan of chunk sums ----------
    if (b == 0) {
        int v = (t < nch) ? g_part[t] : 0;
        sm.s.sh[t] = v;
        __syncthreads();
        for (int off = 1; off < NT; off <<= 1) {
            int xv = (t >= off) ? sm.s.sh[t - off] : 0;
            __syncthreads();
            sm.s.sh[t] += xv;
            __syncthreads();
        }
        if (t < nch) g_partscan[t] = sm.s.sh[t] - v;
    }
    gbar();

    // ---------- P4: rowptr ----------
    for (int c = b; c < nch; c += nb) {
        int i = c * NT + t;
        int v = (i < n) ? g_deg[i] : 0;
        sm.s.sh[t] = v;
        __syncthreads();
        for (int off = 1; off < NT; off <<= 1) {
            int xv = (t >= off) ? sm.s.sh[t - off] : 0;
            __syncthreads();
            sm.s.sh[t] += xv;
            __syncthreads();
        }
        if (i < n) {
            int rp = g_partscan[c] + sm.s.sh[t] - v;
            g_rowptr[i] = rp;
            g_cur[i] = rp;
            if (i == n - 1) g_rowptr[n] = E;
        }
        __syncthreads();
    }
    gbar();

    // ---------- P5: fill CSR ----------
    {
        int is64 = g_is64_e;
        for (long e0 = (long)b * NT + t; e0 < E; e0 += gstride) {
            int src = (int)ldidx(ei, e0, is64);
            int dst = (int)ldidx(ei, (long)E + e0, is64);
            int pos = atomicAdd(&g_cur[dst], 1);
            g_csrc[pos] = src;
        }
    }
    gbar();

    int ntiles = (n + 63) / 64;

    // ---------- P6: layer-0 ----------
    for (int i = t; i < 128; i += NT) sm.l0.st[i] = 0.f;
    __syncthreads();
    for (int tile = b; tile < ntiles; tile += nb) {
        int r0 = tile * 64;
        for (int rr = 0; rr < 4; rr++) {
            int rl = warp * 4 + rr;
            int row = r0 + rl;
            float acc = 0.f;
            if (row < n) {
                int beg = g_rowptr[row], end = g_rowptr[row + 1];
                for (int j = beg + lane; j < end; j += 32)
                    acc += x[g_csrc[j]];
            }
            #pragma unroll
            for (int o = 16; o > 0; o >>= 1)
                acc += __shfl_xor_sync(0xFFFFFFFFu, acc, o);
            if (lane == 0)
                sm.l0.xr[rl] = (row < n) ? (acc + x[row]) : 0.f;
        }
        __syncthreads();
        int c = t & 63, g4 = t >> 6;
        float wc = w1_0[c], bc = b1[c];
        float s = 0.f, q = 0.f;
        #pragma unroll
        for (int i = 0; i < 8; i++) {
            int row = r0 + g4 * 8 + i;
            if (row < n) {
                float zv = sm.l0.xr[g4 * 8 + i] * wc + bc;
                g_z[(size_t)row * HID + c] = zv;
                s += zv; q += zv * zv;
            }
        }
        atomicAdd(&sm.l0.st[c], s);
        atomicAdd(&sm.l0.st[64 + c], q);
        __syncthreads();
    }
    if (t < 128) atomicAdd(&g_statp[slice + t], sm.l0.st[t]);
    gbar();

    // ---------- layers ----------
    for (int l = 0; l < LAY; l++) {
        // ----- gemm1 + half-split prefetched gather (l >= 1) -----
        if (l > 0) {
            int pc = (l - 1) * HID;
            int pso = (l - 1) * 256 + 128;
            if (t < 64) {
                float s1 = 0.f, s2 = 0.f;
                #pragma unroll 4
                for (int sl = 0; sl < NSLICE; sl++) {
                    const float* sp = g_statp + sl * STATSZ + pso;
                    s1 += __ldcg(sp + t);
                    s2 += __ldcg(sp + 64 + t);
                }
                float mean = s1 * invN;
                float var  = s2 * invN - mean * mean;
                float a = go[pc + t] * rsqrtf(var + BN_EPS);
                sm.g.a[t] = a;
                sm.g.b[t] = bo[pc + t] - mean * a;
                sm.g.bias[t] = b1[l * HID + t];
            }
            const float* w = w1_rest + (size_t)(l - 1) * 4096;
            for (int idx = t; idx < 4096; idx += NT)
                sm.g.w[idx >> 6][idx & 63] = w[idx];
            for (int i = t; i < 128; i += NT) sm.g.st[i] = 0.f;
            __syncthreads();

            int half = lane >> 4, c4 = lane & 15;
            float4 ca = *(const float4*)&sm.g.a[c4 * 4];
            float4 cb = *(const float4*)&sm.g.b[c4 * 4];
            const __half* hbase = g_h16 + pc + c4 * 4;
            int so = l * 256;

            for (int tile = b; tile < ntiles; tile += nb) {
                int r0 = tile * 64;
                for (int rr = 0; rr < 4; rr++) {
                    int rl = warp * 4 + rr;
                    int row = r0 + rl;
                    float4 A = make_float4(0.f, 0.f, 0.f, 0.f);
                    auto accum = [&](uint2 raw) {
                        float2 f01 = __half22float2(*(__half2*)&raw.x);
                        float2 f23 = __half22float2(*(__half2*)&raw.y);
                        A.x += fmaxf(fmaf(f01.x, ca.x, cb.x), 0.f);
                        A.y += fmaxf(fmaf(f01.y, ca.y, cb.y), 0.f);
                        A.z += fmaxf(fmaf(f23.x, ca.z, cb.z), 0.f);
                        A.w += fmaxf(fmaf(f23.y, ca.w, cb.w), 0.f);
                    };
                    if (row < n) {
                        int beg = g_rowptr[row], end = g_rowptr[row + 1];
                        int j = beg + half;
                        int rem = end - j;
                        rem = (rem > 0) ? ((rem + 1) >> 1) : 0;  // #edges, stride 2
                        if (rem > 0) {
                            // index prefetch pipeline: csrc loads stay off
                            // the row-load critical path (pad makes them safe)
                            int s0 = g_csrc[j];
                            int s1 = g_csrc[j + 2];
                            while (rem > 2) {
                                int n0 = g_csrc[j + 4];
                                int n1 = g_csrc[j + 6];
                                uint2 w0 = *(const uint2*)(hbase + (size_t)s0 * HL);
                                uint2 w1 = *(const uint2*)(hbase + (size_t)s1 * HL);
                                accum(w0);
                                accum(w1);
                                s0 = n0; s1 = n1; j += 4; rem -= 2;
                            }
                            uint2 w0 = *(const uint2*)(hbase + (size_t)s0 * HL);
                            accum(w0);
                            if (rem == 2) {
                                uint2 w1 = *(const uint2*)(hbase + (size_t)s1 * HL);
                                accum(w1);
                            }
                        }
                    }
                    A.x += __shfl_xor_sync(0xFFFFFFFFu, A.x, 16);
                    A.y += __shfl_xor_sync(0xFFFFFFFFu, A.y, 16);
                    A.z += __shfl_xor_sync(0xFFFFFFFFu, A.z, 16);
                    A.w += __shfl_xor_sync(0xFFFFFFFFu, A.w, 16);
                    if (half == 0) {
                        if (row < n) {
                            uint2 raw = *(const uint2*)(hbase + (size_t)row * HL);
                            accum(raw);
                        }
                        float* ip = &sm.g.in[rl][c4 * 4];
                        ip[0] = A.x; ip[1] = A.y; ip[2] = A.z; ip[3] = A.w;
                    }
                }
                __syncthreads();
                // GEMM: 512 threads, 8 outputs each
                int r = t & 63, c0 = (t >> 6) * 8;
                float acc[8];
                #pragma unroll
                for (int j = 0; j < 8; j++) acc[j] = sm.g.bias[c0 + j];
                #pragma unroll
                for (int k = 0; k < 64; k++) {
                    float a = sm.g.in[r][k];
                    float4 wv0 = *(const float4*)&sm.g.w[k][c0];
                    float4 wv1 = *(const float4*)&sm.g.w[k][c0 + 4];
                    acc[0] = fmaf(a, wv0.x, acc[0]);
                    acc[1] = fmaf(a, wv0.y, acc[1]);
                    acc[2] = fmaf(a, wv0.z, acc[2]);
                    acc[3] = fmaf(a, wv0.w, acc[3]);
                    acc[4] = fmaf(a, wv1.x, acc[4]);
                    acc[5] = fmaf(a, wv1.y, acc[5]);
                    acc[6] = fmaf(a, wv1.z, acc[6]);
                    acc[7] = fmaf(a, wv1.w, acc[7]);
                }
                int gr = r0 + r;
                bool valid = gr < n;
                if (valid) {
                    float4* op = (float4*)&g_z[(size_t)gr * HID + c0];
                    op[0] = make_float4(acc[0], acc[1], acc[2], acc[3]);
                    op[1] = make_float4(acc[4], acc[5], acc[6], acc[7]);
                }
                #pragma unroll
                for (int j = 0; j < 8; j++) {
                    float s = valid ? acc[j] : 0.f;
                    float q = s * s;
                    #pragma unroll
                    for (int o = 16; o > 0; o >>= 1) {
                        s += __shfl_down_sync(0xFFFFFFFFu, s, o);
                        q += __shfl_down_sync(0xFFFFFFFFu, q, o);
                    }
                    if (lane == 0) {
                        atomicAdd(&sm.g.st[c0 + j], s);
                        atomicAdd(&sm.g.st[64 + c0 + j], q);
                    }
                }
                __syncthreads();
            }
            if (t < 128) atomicAdd(&g_statp[slice + so + t], sm.g.st[t]);
            gbar();
        }

        // ----- gemm2: fp32 z in, fp16 h out -----
        {
            int zso = l * 256;
            if (t < 64) {
                float s1 = 0.f, s2 = 0.f;
                #pragma unroll 4
                for (int sl = 0; sl < NSLICE; sl++) {
                    const float* sp = g_statp + sl * STATSZ + zso;
                    s1 += __ldcg(sp + t);
                    s2 += __ldcg(sp + 64 + t);
                }
                float mean = s1 * invN;
                float var  = s2 * invN - mean * mean;
                float a = gm[l * HID + t] * rsqrtf(var + BN_EPS);
                sm.g.a[t] = a;
                sm.g.b[t] = bm[l * HID + t] - mean * a;
                sm.g.bias[t] = b2[l * HID + t];
            }
            const float* w = w2 + (size_t)l * 4096;
            for (int idx = t; idx < 4096; idx += NT)
                sm.g.w[idx >> 6][idx & 63] = w[idx];
            for (int i = t; i < 128; i += NT) sm.g.st[i] = 0.f;
            __syncthreads();

            int vso = l * 256 + 128;

            for (int tile = b; tile < ntiles; tile += nb) {
                int r0 = tile * 64;
                for (int idx = t; idx < 1024; idx += NT) {
                    int r = idx >> 4, k4 = idx & 15;
                    int gr = r0 + r;
                    float4 val = make_float4(0.f, 0.f, 0.f, 0.f);
                    if (gr < n) {
                        float4 z = *(const float4*)(g_z + (size_t)gr * HID + k4 * 4);
                        val.x = fmaxf(fmaf(z.x, sm.g.a[k4*4+0], sm.g.b[k4*4+0]), 0.f);
                        val.y = fmaxf(fmaf(z.y, sm.g.a[k4*4+1], sm.g.b[k4*4+1]), 0.f);
                        val.z = fmaxf(fmaf(z.z, sm.g.a[k4*4+2], sm.g.b[k4*4+2]), 0.f);
                        val.w = fmaxf(fmaf(z.w, sm.g.a[k4*4+3], sm.g.b[k4*4+3]), 0.f);
                    }
                    sm.g.in[r][k4*4+0] = val.x;
                    sm.g.in[r][k4*4+1] = val.y;
                    sm.g.in[r][k4*4+2] = val.z;
                    sm.g.in[r][k4*4+3] = val.w;
                }
                __syncthreads();
                int r = t & 63, c0 = (t >> 6) * 8;
                float acc[8];
                #pragma unroll
                for (int j = 0; j < 8; j++) acc[j] = sm.g.bias[c0 + j];
                #pragma unroll
                for (int k = 0; k < 64; k++) {
                    float a = sm.g.in[r][k];
                    float4 wv0 = *(const float4*)&sm.g.w[k][c0];
                    float4 wv1 = *(const float4*)&sm.g.w[k][c0 + 4];
                    acc[0] = fmaf(a, wv0.x, acc[0]);
                    acc[1] = fmaf(a, wv0.y, acc[1]);
                    acc[2] = fmaf(a, wv0.z, acc[2]);
                    acc[3] = fmaf(a, wv0.w, acc[3]);
                    acc[4] = fmaf(a, wv1.x, acc[4]);
                    acc[5] = fmaf(a, wv1.y, acc[5]);
                    acc[6] = fmaf(a, wv1.z, acc[6]);
                    acc[7] = fmaf(a, wv1.w, acc[7]);
                }
                int gr = r0 + r;
                bool valid = gr < n;
                if (valid) {
                    uint4 pk;
                    __half2* ph = (__half2*)&pk;
                    ph[0] = __float22half2_rn(make_float2(acc[0], acc[1]));
                    ph[1] = __float22half2_rn(make_float2(acc[2], acc[3]));
                    ph[2] = __float22half2_rn(make_float2(acc[4], acc[5]));
                    ph[3] = __float22half2_rn(make_float2(acc[6], acc[7]));
                    *(uint4*)(g_h16 + (size_t)gr * HL + l * HID + c0) = pk;
                }
                #pragma unroll
                for (int j = 0; j < 8; j++) {
                    float s = valid ? acc[j] : 0.f;
                    float q = s * s;
                    #pragma unroll
                    for (int o = 16; o > 0; o >>= 1) {
                        s += __shfl_down_sync(0xFFFFFFFFu, s, o);
                        q += __shfl_down_sync(0xFFFFFFFFu, q, o);
                    }
                    if (lane == 0) {
                        atomicAdd(&sm.g.st[c0 + j], s);
                        atomicAdd(&sm.g.st[64 + c0 + j], q);
                    }
                }
                __syncthreads();
            }
            if (t < 128) atomicAdd(&g_statp[slice + vso + t], sm.g.st[t]);
            gbar();
        }
    }

    // ---------- pool + classifier ----------
    for (int c = t; c < HL; c += NT) {
        int l = c >> 6, ch = c & 63;
        int vso = l * 256 + 128;
        float s1 = 0.f, s2 = 0.f;
        for (int sl = 0; sl < NSLICE; sl++) {
            const float* sp = g_statp + sl * STATSZ + vso;
            s1 += __ldcg(sp + ch);
            s2 += __ldcg(sp + 64 + ch);
        }
        float mean = s1 * invN;
        float var  = s2 * invN - mean * mean;
        float a = go[c] * rsqrtf(var + BN_EPS);
        sm.p.a[c] = a;
        sm.p.b[c] = bo[c] - mean * a;
    }
    __syncthreads();
    {
        int is64 = g_is64_b;
        int warpsTotal = nb * 16;
        int gw = b * 16 + warp;
        for (int g = gw; g < GNUM; g += warpsTotal) {
            int se = n;
            if (lane < 2) {
                int key = g + lane;
                int lo = 0, hi = n;
                while (lo < hi) {
                    int mid = (lo + hi) >> 1;
                    if ((int)ldidx(batch, mid, is64) < key) lo = mid + 1;
                    else hi = mid;
                }
                se = lo;
            }
            int s0 = __shfl_sync(0xFFFFFFFFu, se, 0);
            int e0 = __shfl_sync(0xFFFFFFFFu, se, 1);
            float acc0[5], acc1[5];
            #pragma unroll
            for (int k = 0; k < 5; k++) { acc0[k] = 0.f; acc1[k] = 0.f; }
            float xsum = 0.f;
            int cbase = lane * 2;
            for (int r = s0; r < e0; r++) {
                xsum += x[r];
                const __half2* rp = (const __half2*)(g_h16 + (size_t)r * HL);
                #pragma unroll
                for (int k = 0; k < 5; k++) {
                    float2 f = __half22float2(rp[k * 32 + lane]);
                    int c = k * 64 + cbase;
                    acc0[k] += fmaxf(fmaf(f.x, sm.p.a[c], sm.p.b[c]), 0.f);
                    acc1[k] += fmaxf(fmaf(f.y, sm.p.a[c + 1], sm.p.b[c + 1]), 0.f);
                }
            }
            float o0 = 0.f, o1 = 0.f;
            #pragma unroll
            for (int k = 0; k < 5; k++) {
                int c = k * 64 + cbase;
                o0 = fmaf(acc0[k], lin_w[(1 + c) * 2 + 0], o0);
                o1 = fmaf(acc0[k], lin_w[(1 + c) * 2 + 1], o1);
                o0 = fmaf(acc1[k], lin_w[(2 + c) * 2 + 0], o0);
                o1 = fmaf(acc1[k], lin_w[(2 + c) * 2 + 1], o1);
            }
            #pragma unroll
            for (int o = 16; o > 0; o >>= 1) {
                o0 += __shfl_down_sync(0xFFFFFFFFu, o0, o);
                o1 += __shfl_down_sync(0xFFFFFFFFu, o1, o);
            }
            if (lane == 0) {
                out[g * 2 + 0] = o0 + xsum * lin_w[0] + lin_b[0];
                out[g * 2 + 1] = o1 + xsum * lin_w[1] + lin_b[1];
            }
        }
    }
}

// ---------------- launch ----------------
extern "C" void kernel_launch(void* const* d_in, const int* in_sizes, int n_in,
                              void* d_out, int out_size)
{
    const float* x      = (const float*)d_in[0];
    const void*  ei     = d_in[1];
    const void*  batch  = d_in[2];
    const float* w1_0   = (const float*)d_in[3];
    const float* w1_rest= (const float*)d_in[4];
    const float* b1     = (const float*)d_in[5];
    const float* gm     = (const float*)d_in[6];
    const float* bm     = (const float*)d_in[7];
    const float* w2     = (const float*)d_in[8];
    const float* b2     = (const float*)d_in[9];
    const float* go     = (const float*)d_in[10];
    const float* bo     = (const float*)d_in[11];
    const float* lin_w  = (const float*)d_in[12];
    const float* lin_b  = (const float*)d_in[13];
    float* out = (float*)d_out;

    int N = in_sizes[0];
    int E = in_sizes[1] / 2;
    float invN = 1.f / (float)N;

    fused_all<<<PB, NT>>>(x, ei, batch, w1_0, w1_rest, b1, gm, bm,
                          w2, b2, go, bo, lin_w, lin_b, out,
                          N, E, in_sizes[2], invN);
}

// round 15
// speedup vs baseline: 1.1795x; 1.0963x over previous
#include <cuda_runtime.h>
#include <cuda_fp16.h>
#include <cstdint>

#define NMAX 50000
#define EMAX 800000
#define GNUM 512
#define HID 64
#define LAY 5
#define HL 320
#define BN_EPS 1e-5f
#define PB 444
#define NT 512
#define NSLICE 16
#define STATSZ (LAY * 256)

// ---------------- static scratch ----------------
__device__ float  g_z[(size_t)NMAX * HID];      // post-GEMM1 pre-BN z, fp32
__device__ __half g_h16[(size_t)NMAX * HL];     // RAW gemm2 outputs (pre-BN), fp16
__device__ float  g_statp[NSLICE * STATSZ];
__device__ int    g_deg[NMAX];
__device__ int    g_rowptr[NMAX + 1];
__device__ int    g_cur[NMAX];
__device__ int    g_part[256];
__device__ int    g_partscan[256];
__device__ int    g_csrc[EMAX + 8];
__device__ int    g_is64_e, g_is64_b;
__device__ unsigned g_count = 0, g_epoch = 0;

__device__ __forceinline__ long ldidx(const void* p, long i, int is64) {
    return is64 ? (long)((const long long*)p)[i] : (long)((const int*)p)[i];
}

__device__ __forceinline__ unsigned ld_epoch() {
    unsigned v;
    asm volatile("ld.global.cg.u32 %0, [%1];" : "=r"(v) : "l"(&g_epoch) : "memory");
    return v;
}

__device__ __forceinline__ void gbar() {
    __syncthreads();
    if (threadIdx.x == 0) {
        __threadfence();
        unsigned e = ld_epoch();
        if (atomicAdd(&g_count, 1) == gridDim.x - 1) {
            atomicExch(&g_count, 0u);
            __threadfence();
            atomicExch(&g_epoch, e + 1);
        } else {
            unsigned cur;
            do { __nanosleep(20); cur = ld_epoch(); } while (cur == e);
        }
        __threadfence();
    }
    __syncthreads();
}

// ---------------- shared memory ----------------
struct SmGemm {
    __half w16[64 * 64];     // 8KB fp16 weights, row k, col c
    float in[128][65];       // 33.3KB staged input tile (128 rows)
    float a[64];
    float b[64];
    float bias[64];
    float st[128];
};
struct SmPool { float a[HL]; float b[HL]; };
struct SmScan { int sh[NT + 1]; };
struct SmL0   { float xr[64]; float st[128]; };
union __align__(16) SmU {
    SmGemm g; SmPool p; SmScan s; SmL0 l0;
};

__global__ void __launch_bounds__(NT, 3) fused_all(
    const float* __restrict__ x, const void* __restrict__ ei,
    const void* __restrict__ batch,
    const float* __restrict__ w1_0, const float* __restrict__ w1_rest,
    const float* __restrict__ b1,
    const float* __restrict__ gm, const float* __restrict__ bm,
    const float* __restrict__ w2, const float* __restrict__ b2,
    const float* __restrict__ go, const float* __restrict__ bo,
    const float* __restrict__ lin_w, const float* __restrict__ lin_b,
    float* __restrict__ out, int n, int E, int bcount, float invN)
{
    __shared__ SmU sm;
    int t = threadIdx.x, b = blockIdx.x, nb = gridDim.x;
    int lane = t & 31, warp = t >> 5;
    long gstride = (long)nb * NT;
    int slice = (b & (NSLICE - 1)) * STATSZ;

    // ---------- P0: zero + detect ----------
    for (long i = (long)b * NT + t; i < n; i += gstride) g_deg[i] = 0;
    for (long i = (long)b * NT + t; i < NSLICE * STATSZ; i += gstride) g_statp[i] = 0.f;
    if (b == 1) {
        const int* p = (const int*)ei;
        int f = 0;
        for (int i = t; i < 4096; i += NT) if (p[2 * i + 1] != 0) f = 1;
        f = __syncthreads_or(f);
        if (t == 0) g_is64_e = (f == 0);
        const int* q = (const int*)batch;
        int hf = bcount / 2;
        int f2 = 0;
        for (int i = t; i < 2048; i += NT) {
            int pos = hf - 1 - i;
            if (pos >= 0 && q[2 * pos + 1] != 0) f2 = 1;
        }
        f2 = __syncthreads_or(f2);
        if (t == 0) g_is64_b = (f2 == 0);
    }
    gbar();

    // ---------- P1: degree histogram ----------
    {
        int is64 = g_is64_e;
        for (long e0 = (long)b * NT + t; e0 < E; e0 += gstride) {
            int dst = (int)ldidx(ei, (long)E + e0, is64);
            atomicAdd(&g_deg[dst], 1);
        }
    }
    gbar();

    int nch = (n + NT - 1) / NT;

    // ---------- P2: chunk sums ----------
    for (int c = b; c < nch; c += nb) {
        int i = c * NT + t;
        sm.s.sh[t] = (i < n) ? g_deg[i] : 0;
        __syncthreads();
        for (int off = NT / 2; off > 0; off >>= 1) {
            if (t < off) sm.s.sh[t] += sm.s.sh[t + off];
            __syncthreads();
        }
        if (t == 0) g_part[c] = sm.s.sh[0];
        __syncthreads();
    }
    gbar();

    // ---------- P3: scan of chunk sums ----------
    if (b == 0) {
        int v = (t < nch) ? g_part[t] : 0;
        sm.s.sh[t] = v;
        __syncthreads();
        for (int off = 1; off < NT; off <<= 1) {
            int xv = (t >= off) ? sm.s.sh[t - off] : 0;
            __syncthreads();
            sm.s.sh[t] += xv;
            __syncthreads();
        }
        if (t < nch) g_partscan[t] = sm.s.sh[t] - v;
    }
    gbar();

    // ---------- P4: rowptr ----------
    for (int c = b; c < nch; c += nb) {
        int i = c * NT + t;
        int v = (i < n) ? g_deg[i] : 0;
        sm.s.sh[t] = v;
        __syncthreads();
        for (int off = 1; off < NT; off <<= 1) {
            int xv = (t >= off) ? sm.s.sh[t - off] : 0;
            __syncthreads();
            sm.s.sh[t] += xv;
            __syncthreads();
        }
        if (i < n) {
            int rp = g_partscan[c] + sm.s.sh[t] - v;
            g_rowptr[i] = rp;
            g_cur[i] = rp;
            if (i == n - 1) g_rowptr[n] = E;
        }
        __syncthreads();
    }
    gbar();

    // ---------- P5: fill CSR ----------
    {
        int is64 = g_is64_e;
        for (long e0 = (long)b * NT + t; e0 < E; e0 += gstride) {
            int src = (int)ldidx(ei, e0, is64);
            int dst = (int)ldidx(ei, (long)E + e0, is64);
            int pos = atomicAdd(&g_cur[dst], 1);
            g_csrc[pos] = src;
        }
    }
    gbar();

    int ntiles = (n + 63) / 64;    // layer-0: 64-row tiles
    int ntile2 = (n + 127) >> 7;   // GEMM: 128-row tiles

    // ---------- P6: layer-0 ----------
    for (int i = t; i < 128; i += NT) sm.l0.st[i] = 0.f;
    __syncthreads();
    for (int tile = b; tile < ntiles; tile += nb) {
        int r0 = tile * 64;
        for (int rr = 0; rr < 4; rr++) {
            int rl = warp * 4 + rr;
            int row = r0 + rl;
            float acc = 0.f;
            if (row < n) {
                int beg = g_rowptr[row], end = g_rowptr[row + 1];
                for (int j = beg + lane; j < end; j += 32)
                    acc += x[g_csrc[j]];
            }
            #pragma unroll
            for (int o = 16; o > 0; o >>= 1)
                acc += __shfl_xor_sync(0xFFFFFFFFu, acc, o);
            if (lane == 0)
                sm.l0.xr[rl] = (row < n) ? (acc + x[row]) : 0.f;
        }
        __syncthreads();
        int c = t & 63, g4 = t >> 6;
        float wc = w1_0[c], bc = b1[c];
        float s = 0.f, q = 0.f;
        #pragma unroll
        for (int i = 0; i < 8; i++) {
            int row = r0 + g4 * 8 + i;
            if (row < n) {
                float zv = sm.l0.xr[g4 * 8 + i] * wc + bc;
                g_z[(size_t)row * HID + c] = zv;
                s += zv; q += zv * zv;
            }
        }
        atomicAdd(&sm.l0.st[c], s);
        atomicAdd(&sm.l0.st[64 + c], q);
        __syncthreads();
    }
    if (t < 128) atomicAdd(&g_statp[slice + t], sm.l0.st[t]);
    gbar();

    // ---------- layers ----------
    for (int l = 0; l < LAY; l++) {
        // ===== gemm1 + gather (l >= 1), 128-row tiles =====
        if (l > 0) {
            int pc = (l - 1) * HID;
            int pso = (l - 1) * 256 + 128;
            if (t < 64) {
                float s1 = 0.f, s2 = 0.f;
                #pragma unroll 4
                for (int sl = 0; sl < NSLICE; sl++) {
                    const float* sp = g_statp + sl * STATSZ + pso;
                    s1 += __ldcg(sp + t);
                    s2 += __ldcg(sp + 64 + t);
                }
                float mean = s1 * invN;
                float var  = s2 * invN - mean * mean;
                float a = go[pc + t] * rsqrtf(var + BN_EPS);
                sm.g.a[t] = a;
                sm.g.b[t] = bo[pc + t] - mean * a;
                sm.g.bias[t] = b1[l * HID + t];
            }
            {
                const float* w = w1_rest + (size_t)(l - 1) * 4096;
                for (int idx = t; idx < 4096; idx += NT)
                    sm.g.w16[idx] = __float2half(w[idx]);
            }
            for (int i = t; i < 128; i += NT) sm.g.st[i] = 0.f;
            __syncthreads();

            int half = lane >> 4, c4 = lane & 15;
            float4 ca = *(const float4*)&sm.g.a[c4 * 4];
            float4 cb = *(const float4*)&sm.g.b[c4 * 4];
            const __half* hbase = g_h16 + pc + c4 * 4;
            int so = l * 256;

            for (int tile = b; tile < ntile2; tile += nb) {
                int r0 = tile << 7;
                // gather: 16 warps x 8 rows = 128 rows
                for (int rr = 0; rr < 8; rr++) {
                    int rl = warp * 8 + rr;
                    int row = r0 + rl;
                    float4 A = make_float4(0.f, 0.f, 0.f, 0.f);
                    auto accum = [&](uint2 raw) {
                        float2 f01 = __half22float2(*(__half2*)&raw.x);
                        float2 f23 = __half22float2(*(__half2*)&raw.y);
                        A.x += fmaxf(fmaf(f01.x, ca.x, cb.x), 0.f);
                        A.y += fmaxf(fmaf(f01.y, ca.y, cb.y), 0.f);
                        A.z += fmaxf(fmaf(f23.x, ca.z, cb.z), 0.f);
                        A.w += fmaxf(fmaf(f23.y, ca.w, cb.w), 0.f);
                    };
                    if (row < n) {
                        int beg = g_rowptr[row], end = g_rowptr[row + 1];
                        int j = beg + half;
                        while (j + 2 < end) {
                            int s0 = g_csrc[j];
                            int s1 = g_csrc[j + 2];
                            uint2 w0 = *(const uint2*)(hbase + (size_t)s0 * HL);
                            uint2 w1 = *(const uint2*)(hbase + (size_t)s1 * HL);
                            accum(w0);
                            accum(w1);
                            j += 4;
                        }
                        if (j < end) {
                            int s0 = g_csrc[j];
                            uint2 w0 = *(const uint2*)(hbase + (size_t)s0 * HL);
                            accum(w0);
                        }
                    }
                    A.x += __shfl_xor_sync(0xFFFFFFFFu, A.x, 16);
                    A.y += __shfl_xor_sync(0xFFFFFFFFu, A.y, 16);
                    A.z += __shfl_xor_sync(0xFFFFFFFFu, A.z, 16);
                    A.w += __shfl_xor_sync(0xFFFFFFFFu, A.w, 16);
                    if (half == 0) {
                        if (row < n) {
                            uint2 raw = *(const uint2*)(hbase + (size_t)row * HL);
                            accum(raw);
                        }
                        float* ip = &sm.g.in[rl][c4 * 4];
                        ip[0] = A.x; ip[1] = A.y; ip[2] = A.z; ip[3] = A.w;
                    }
                }
                __syncthreads();
                // GEMM: 2 rows x 8 cols per thread
                int r = t & 63, c0 = (t >> 6) * 8;
                float accA[8], accB[8];
                #pragma unroll
                for (int j = 0; j < 8; j++) { accA[j] = sm.g.bias[c0 + j]; accB[j] = accA[j]; }
                #pragma unroll
                for (int k = 0; k < 64; k++) {
                    float a0 = sm.g.in[r][k];
                    float a1 = sm.g.in[r + 64][k];
                    uint4 wr = *(const uint4*)&sm.g.w16[k * 64 + c0];
                    const __half2* wh = (const __half2*)&wr;
                    #pragma unroll
                    for (int m = 0; m < 4; m++) {
                        float2 f = __half22float2(wh[m]);
                        accA[2*m]   = fmaf(a0, f.x, accA[2*m]);
                        accA[2*m+1] = fmaf(a0, f.y, accA[2*m+1]);
                        accB[2*m]   = fmaf(a1, f.x, accB[2*m]);
                        accB[2*m+1] = fmaf(a1, f.y, accB[2*m+1]);
                    }
                }
                int gr0 = r0 + r, gr1 = r0 + r + 64;
                bool v0 = gr0 < n, v1 = gr1 < n;
                if (v0) {
                    float4* op = (float4*)&g_z[(size_t)gr0 * HID + c0];
                    op[0] = make_float4(accA[0], accA[1], accA[2], accA[3]);
                    op[1] = make_float4(accA[4], accA[5], accA[6], accA[7]);
                }
                if (v1) {
                    float4* op = (float4*)&g_z[(size_t)gr1 * HID + c0];
                    op[0] = make_float4(accB[0], accB[1], accB[2], accB[3]);
                    op[1] = make_float4(accB[4], accB[5], accB[6], accB[7]);
                }
                #pragma unroll
                for (int j = 0; j < 8; j++) {
                    float s = (v0 ? accA[j] : 0.f) + (v1 ? accB[j] : 0.f);
                    float q = (v0 ? accA[j] * accA[j] : 0.f) + (v1 ? accB[j] * accB[j] : 0.f);
                    #pragma unroll
                    for (int o = 16; o > 0; o >>= 1) {
                        s += __shfl_down_sync(0xFFFFFFFFu, s, o);
                        q += __shfl_down_sync(0xFFFFFFFFu, q, o);
                    }
                    if (lane == 0) {
                        atomicAdd(&sm.g.st[c0 + j], s);
                        atomicAdd(&sm.g.st[64 + c0 + j], q);
                    }
                }
                __syncthreads();
            }
            if (t < 128) atomicAdd(&g_statp[slice + so + t], sm.g.st[t]);
            gbar();
        }

        // ===== gemm2: 128-row tiles, fp32 z in, fp16 h out =====
        {
            int zso = l * 256;
            if (t < 64) {
                float s1 = 0.f, s2 = 0.f;
                #pragma unroll 4
                for (int sl = 0; sl < NSLICE; sl++) {
                    const float* sp = g_statp + sl * STATSZ + zso;
                    s1 += __ldcg(sp + t);
                    s2 += __ldcg(sp + 64 + t);
                }
                float mean = s1 * invN;
                float var  = s2 * invN - mean * mean;
                float a = gm[l * HID + t] * rsqrtf(var + BN_EPS);
                sm.g.a[t] = a;
                sm.g.b[t] = bm[l * HID + t] - mean * a;
                sm.g.bias[t] = b2[l * HID + t];
            }
            {
                const float* w = w2 + (size_t)l * 4096;
                for (int idx = t; idx < 4096; idx += NT)
                    sm.g.w16[idx] = __float2half(w[idx]);
            }
            for (int i = t; i < 128; i += NT) sm.g.st[i] = 0.f;
            __syncthreads();

            int vso = l * 256 + 128;

            for (int tile = b; tile < ntile2; tile += nb) {
                int r0 = tile << 7;
                for (int idx = t; idx < 2048; idx += NT) {
                    int r = idx >> 4, k4 = idx & 15;
                    int gr = r0 + r;
                    float4 val = make_float4(0.f, 0.f, 0.f, 0.f);
                    if (gr < n) {
                        float4 z = *(const float4*)(g_z + (size_t)gr * HID + k4 * 4);
                        val.x = fmaxf(fmaf(z.x, sm.g.a[k4*4+0], sm.g.b[k4*4+0]), 0.f);
                        val.y = fmaxf(fmaf(z.y, sm.g.a[k4*4+1], sm.g.b[k4*4+1]), 0.f);
                        val.z = fmaxf(fmaf(z.z, sm.g.a[k4*4+2], sm.g.b[k4*4+2]), 0.f);
                        val.w = fmaxf(fmaf(z.w, sm.g.a[k4*4+3], sm.g.b[k4*4+3]), 0.f);
                    }
                    sm.g.in[r][k4*4+0] = val.x;
                    sm.g.in[r][k4*4+1] = val.y;
                    sm.g.in[r][k4*4+2] = val.z;
                    sm.g.in[r][k4*4+3] = val.w;
                }
                __syncthreads();
                int r = t & 63, c0 = (t >> 6) * 8;
                float accA[8], accB[8];
                #pragma unroll
                for (int j = 0; j < 8; j++) { accA[j] = sm.g.bias[c0 + j]; accB[j] = accA[j]; }
                #pragma unroll
                for (int k = 0; k < 64; k++) {
                    float a0 = sm.g.in[r][k];
                    float a1 = sm.g.in[r + 64][k];
                    uint4 wr = *(const uint4*)&sm.g.w16[k * 64 + c0];
                    const __half2* wh = (const __half2*)&wr;
                    #pragma unroll
                    for (int m = 0; m < 4; m++) {
                        float2 f = __half22float2(wh[m]);
                        accA[2*m]   = fmaf(a0, f.x, accA[2*m]);
                        accA[2*m+1] = fmaf(a0, f.y, accA[2*m+1]);
                        accB[2*m]   = fmaf(a1, f.x, accB[2*m]);
                        accB[2*m+1] = fmaf(a1, f.y, accB[2*m+1]);
                    }
                }
                int gr0 = r0 + r, gr1 = r0 + r + 64;
                bool v0 = gr0 < n, v1 = gr1 < n;
                if (v0) {
                    uint4 pk;
                    __half2* ph = (__half2*)&pk;
                    ph[0] = __float22half2_rn(make_float2(accA[0], accA[1]));
                    ph[1] = __float22half2_rn(make_float2(accA[2], accA[3]));
                    ph[2] = __float22half2_rn(make_float2(accA[4], accA[5]));
                    ph[3] = __float22half2_rn(make_float2(accA[6], accA[7]));
                    *(uint4*)(g_h16 + (size_t)gr0 * HL + l * HID + c0) = pk;
                }
                if (v1) {
                    uint4 pk;
                    __half2* ph = (__half2*)&pk;
                    ph[0] = __float22half2_rn(make_float2(accB[0], accB[1]));
                    ph[1] = __float22half2_rn(make_float2(accB[2], accB[3]));
                    ph[2] = __float22half2_rn(make_float2(accB[4], accB[5]));
                    ph[3] = __float22half2_rn(make_float2(accB[6], accB[7]));
                    *(uint4*)(g_h16 + (size_t)gr1 * HL + l * HID + c0) = pk;
                }
                #pragma unroll
                for (int j = 0; j < 8; j++) {
                    float s = (v0 ? accA[j] : 0.f) + (v1 ? accB[j] : 0.f);
                    float q = (v0 ? accA[j] * accA[j] : 0.f) + (v1 ? accB[j] * accB[j] : 0.f);
                    #pragma unroll
                    for (int o = 16; o > 0; o >>= 1) {
                        s += __shfl_down_sync(0xFFFFFFFFu, s, o);
                        q += __shfl_down_sync(0xFFFFFFFFu, q, o);
                    }
                    if (lane == 0) {
                        atomicAdd(&sm.g.st[c0 + j], s);
                        atomicAdd(&sm.g.st[64 + c0 + j], q);
                    }
                }
                __syncthreads();
            }
            if (t < 128) atomicAdd(&g_statp[slice + vso + t], sm.g.st[t]);
            gbar();
        }
    }

    // ---------- pool + classifier ----------
    for (int c = t; c < HL; c += NT) {
        int l = c >> 6, ch = c & 63;
        int vso = l * 256 + 128;
        float s1 = 0.f, s2 = 0.f;
        for (int sl = 0; sl < NSLICE; sl++) {
            const float* sp = g_statp + sl * STATSZ + vso;
            s1 += __ldcg(sp + ch);
            s2 += __ldcg(sp + 64 + ch);
        }
        float mean = s1 * invN;
        float var  = s2 * invN - mean * mean;
        float a = go[c] * rsqrtf(var + BN_EPS);
        sm.p.a[c] = a;
        sm.p.b[c] = bo[c] - mean * a;
    }
    __syncthreads();
    {
        int is64 = g_is64_b;
        int warpsTotal = nb * 16;
        int gw = b * 16 + warp;
        for (int g = gw; g < GNUM; g += warpsTotal) {
            int se = n;
            if (lane < 2) {
                int key = g + lane;
                int lo = 0, hi = n;
                while (lo < hi) {
                    int mid = (lo + hi) >> 1;
                    if ((int)ldidx(batch, mid, is64) < key) lo = mid + 1;
                    else hi = mid;
                }
                se = lo;
            }
            int s0 = __shfl_sync(0xFFFFFFFFu, se, 0);
            int e0 = __shfl_sync(0xFFFFFFFFu, se, 1);
            float acc0[5], acc1[5];
            #pragma unroll
            for (int k = 0; k < 5; k++) { acc0[k] = 0.f; acc1[k] = 0.f; }
            float xsum = 0.f;
            int cbase = lane * 2;
            for (int r = s0; r < e0; r++) {
                xsum += x[r];
                const __half2* rp = (const __half2*)(g_h16 + (size_t)r * HL);
                #pragma unroll
                for (int k = 0; k < 5; k++) {
                    float2 f = __half22float2(rp[k * 32 + lane]);
                    int c = k * 64 + cbase;
                    acc0[k] += fmaxf(fmaf(f.x, sm.p.a[c], sm.p.b[c]), 0.f);
                    acc1[k] += fmaxf(fmaf(f.y, sm.p.a[c + 1], sm.p.b[c + 1]), 0.f);
                }
            }
            float o0 = 0.f, o1 = 0.f;
            #pragma unroll
            for (int k = 0; k < 5; k++) {
                int c = k * 64 + cbase;
                o0 = fmaf(acc0[k], lin_w[(1 + c) * 2 + 0], o0);
                o1 = fmaf(acc0[k], lin_w[(1 + c) * 2 + 1], o1);
                o0 = fmaf(acc1[k], lin_w[(2 + c) * 2 + 0], o0);
                o1 = fmaf(acc1[k], lin_w[(2 + c) * 2 + 1], o1);
            }
            #pragma unroll
            for (int o = 16; o > 0; o >>= 1) {
                o0 += __shfl_down_sync(0xFFFFFFFFu, o0, o);
                o1 += __shfl_down_sync(0xFFFFFFFFu, o1, o);
            }
            if (lane == 0) {
                out[g * 2 + 0] = o0 + xsum * lin_w[0] + lin_b[0];
                out[g * 2 + 1] = o1 + xsum * lin_w[1] + lin_b[1];
            }
        }
    }
}

// ---------------- launch ----------------
extern "C" void kernel_launch(void* const* d_in, const int* in_sizes, int n_in,
                              void* d_out, int out_size)
{
    const float* x      = (const float*)d_in[0];
    const void*  ei     = d_in[1];
    const void*  batch  = d_in[2];
    const float* w1_0   = (const float*)d_in[3];
    const float* w1_rest= (const float*)d_in[4];
    const float* b1     = (const float*)d_in[5];
    const float* gm     = (const float*)d_in[6];
    const float* bm     = (const float*)d_in[7];
    const float* w2     = (const float*)d_in[8];
    const float* b2     = (const float*)d_in[9];
    const float* go     = (const float*)d_in[10];
    const float* bo     = (const float*)d_in[11];
    const float* lin_w  = (const float*)d_in[12];
    const float* lin_b  = (const float*)d_in[13];
    float* out = (float*)d_out;

    int N = in_sizes[0];
    int E = in_sizes[1] / 2;
    float invN = 1.f / (float)N;

    fused_all<<<PB, NT>>>(x, ei, batch, w1_0, w1_rest, b1, gm, bm,
                          w2, b2, go, bo, lin_w, lin_b, out,
                          N, E, in_sizes[2], invN);
}

// round 16
// speedup vs baseline: 1.2265x; 1.0398x over previous
#include <cuda_runtime.h>
#include <cuda_fp16.h>
#include <cstdint>

#define NMAX 50000
#define EMAX 800000
#define GNUM 512
#define HID 64
#define LAY 5
#define HL 320
#define BN_EPS 1e-5f
#define PB 444
#define NT 512
#define NSLICE 16
#define STATSZ (LAY * 256)

// ---------------- static scratch ----------------
__device__ __half g_h16[(size_t)NMAX * HL];     // RAW gemm2 outputs (pre-BN), fp16
__device__ float  g_statp[NSLICE * STATSZ];
__device__ int    g_deg[NMAX];
__device__ int    g_rowptr[NMAX + 1];
__device__ int    g_cur[NMAX];
__device__ int    g_part[256];
__device__ int    g_partscan[256];
__device__ int    g_csrc[EMAX + 8];
__device__ int    g_is64_e, g_is64_b;
__device__ unsigned g_count = 0, g_epoch = 0;

__device__ __forceinline__ long ldidx(const void* p, long i, int is64) {
    return is64 ? (long)((const long long*)p)[i] : (long)((const int*)p)[i];
}

__device__ __forceinline__ unsigned ld_epoch() {
    unsigned v;
    asm volatile("ld.global.cg.u32 %0, [%1];" : "=r"(v) : "l"(&g_epoch) : "memory");
    return v;
}

__device__ __forceinline__ void gbar() {
    __syncthreads();
    if (threadIdx.x == 0) {
        __threadfence();
        unsigned e = ld_epoch();
        if (atomicAdd(&g_count, 1) == gridDim.x - 1) {
            atomicExch(&g_count, 0u);
            __threadfence();
            atomicExch(&g_epoch, e + 1);
        } else {
            unsigned cur;
            do { __nanosleep(20); cur = ld_epoch(); } while (cur == e);
        }
        __threadfence();
    }
    __syncthreads();
}

// ---------------- shared memory ----------------
struct SmGemm {
    __half w16[64 * 64];     // 8KB fp16 weights
    float in[128][65];       // 33.3KB tile: gather input / z (persists across gbar)
    float a[64];
    float b[64];
    float bias[64];
    float st[128];
    float xr[128];           // layer-0 aggregated x sums
};
struct SmPool { float a[HL]; float b[HL]; };
struct SmScan { int sh[NT + 1]; };
union __align__(16) SmU {
    SmGemm g; SmPool p; SmScan s;
};

__global__ void __launch_bounds__(NT, 3) fused_all(
    const float* __restrict__ x, const void* __restrict__ ei,
    const void* __restrict__ batch,
    const float* __restrict__ w1_0, const float* __restrict__ w1_rest,
    const float* __restrict__ b1,
    const float* __restrict__ gm, const float* __restrict__ bm,
    const float* __restrict__ w2, const float* __restrict__ b2,
    const float* __restrict__ go, const float* __restrict__ bo,
    const float* __restrict__ lin_w, const float* __restrict__ lin_b,
    float* __restrict__ out, int n, int E, int bcount, float invN)
{
    __shared__ SmU sm;
    int t = threadIdx.x, b = blockIdx.x, nb = gridDim.x;
    int lane = t & 31, warp = t >> 5;
    long gstride = (long)nb * NT;
    int slice = (b & (NSLICE - 1)) * STATSZ;

    // ---------- P0: zero + detect ----------
    for (long i = (long)b * NT + t; i < n; i += gstride) g_deg[i] = 0;
    for (long i = (long)b * NT + t; i < NSLICE * STATSZ; i += gstride) g_statp[i] = 0.f;
    if (b == 1) {
        const int* p = (const int*)ei;
        int f = 0;
        for (int i = t; i < 4096; i += NT) if (p[2 * i + 1] != 0) f = 1;
        f = __syncthreads_or(f);
        if (t == 0) g_is64_e = (f == 0);
        const int* q = (const int*)batch;
        int hf = bcount / 2;
        int f2 = 0;
        for (int i = t; i < 2048; i += NT) {
            int pos = hf - 1 - i;
            if (pos >= 0 && q[2 * pos + 1] != 0) f2 = 1;
        }
        f2 = __syncthreads_or(f2);
        if (t == 0) g_is64_b = (f2 == 0);
    }
    gbar();

    // ---------- P1: degree histogram ----------
    {
        int is64 = g_is64_e;
        for (long e0 = (long)b * NT + t; e0 < E; e0 += gstride) {
            int dst = (int)ldidx(ei, (long)E + e0, is64);
            atomicAdd(&g_deg[dst], 1);
        }
    }
    gbar();

    int nch = (n + NT - 1) / NT;

    // ---------- P2: chunk sums ----------
    for (int c = b; c < nch; c += nb) {
        int i = c * NT + t;
        sm.s.sh[t] = (i < n) ? g_deg[i] : 0;
        __syncthreads();
        for (int off = NT / 2; off > 0; off >>= 1) {
            if (t < off) sm.s.sh[t] += sm.s.sh[t + off];
            __syncthreads();
        }
        if (t == 0) g_part[c] = sm.s.sh[0];
        __syncthreads();
    }
    gbar();

    // ---------- P3: scan of chunk sums ----------
    if (b == 0) {
        int v = (t < nch) ? g_part[t] : 0;
        sm.s.sh[t] = v;
        __syncthreads();
        for (int off = 1; off < NT; off <<= 1) {
            int xv = (t >= off) ? sm.s.sh[t - off] : 0;
            __syncthreads();
            sm.s.sh[t] += xv;
            __syncthreads();
        }
        if (t < nch) g_partscan[t] = sm.s.sh[t] - v;
    }
    gbar();

    // ---------- P4: rowptr ----------
    for (int c = b; c < nch; c += nb) {
        int i = c * NT + t;
        int v = (i < n) ? g_deg[i] : 0;
        sm.s.sh[t] = v;
        __syncthreads();
        for (int off = 1; off < NT; off <<= 1) {
            int xv = (t >= off) ? sm.s.sh[t - off] : 0;
            __syncthreads();
            sm.s.sh[t] += xv;
            __syncthreads();
        }
        if (i < n) {
            int rp = g_partscan[c] + sm.s.sh[t] - v;
            g_rowptr[i] = rp;
            g_cur[i] = rp;
            if (i == n - 1) g_rowptr[n] = E;
        }
        __syncthreads();
    }
    gbar();

    // ---------- P5: fill CSR ----------
    {
        int is64 = g_is64_e;
        for (long e0 = (long)b * NT + t; e0 < E; e0 += gstride) {
            int src = (int)ldidx(ei, e0, is64);
            int dst = (int)ldidx(ei, (long)E + e0, is64);
            int pos = atomicAdd(&g_cur[dst], 1);
            g_csrc[pos] = src;
        }
    }
    gbar();

    int ntile2 = (n + 127) >> 7;   // 128-row tiles; ntile2 <= PB

    // ---------- P6: layer-0 (one 128-row tile per block, z -> smem) ----------
    for (int i = t; i < 128; i += NT) sm.g.st[i] = 0.f;
    __syncthreads();
    if (b < ntile2) {
        int r0 = b << 7;
        for (int rr = 0; rr < 8; rr++) {
            int rl = warp * 8 + rr;
            int row = r0 + rl;
            float acc = 0.f;
            if (row < n) {
                int beg = g_rowptr[row], end = g_rowptr[row + 1];
                for (int j = beg + lane; j < end; j += 32)
                    acc += x[g_csrc[j]];
            }
            #pragma unroll
            for (int o = 16; o > 0; o >>= 1)
                acc += __shfl_xor_sync(0xFFFFFFFFu, acc, o);
            if (lane == 0)
                sm.g.xr[rl] = (row < n) ? (acc + x[row]) : 0.f;
        }
        __syncthreads();
        int c = t & 63, g4 = t >> 6;
        float wc = w1_0[c], bc = b1[c];
        float s = 0.f, q = 0.f;
        #pragma unroll
        for (int i = 0; i < 16; i++) {
            int rl = g4 * 16 + i;
            int row = r0 + rl;
            float zv = 0.f;
            if (row < n) {
                zv = sm.g.xr[rl] * wc + bc;
                s += zv; q += zv * zv;
            }
            sm.g.in[rl][c] = zv;
        }
        atomicAdd(&sm.g.st[c], s);
        atomicAdd(&sm.g.st[64 + c], q);
    }
    __syncthreads();
    if (t < 128) atomicAdd(&g_statp[slice + t], sm.g.st[t]);
    gbar();

    // ---------- layers ----------
    for (int l = 0; l < LAY; l++) {
        // ===== gemm1 + gather (l >= 1): z stays in smem =====
        if (l > 0) {
            int pc = (l - 1) * HID;
            int pso = (l - 1) * 256 + 128;
            if (t < 64) {
                float s1 = 0.f, s2 = 0.f;
                #pragma unroll 4
                for (int sl = 0; sl < NSLICE; sl++) {
                    const float* sp = g_statp + sl * STATSZ + pso;
                    s1 += __ldcg(sp + t);
                    s2 += __ldcg(sp + 64 + t);
                }
                float mean = s1 * invN;
                float var  = s2 * invN - mean * mean;
                float a = go[pc + t] * rsqrtf(var + BN_EPS);
                sm.g.a[t] = a;
                sm.g.b[t] = bo[pc + t] - mean * a;
                sm.g.bias[t] = b1[l * HID + t];
            }
            {
                const float* w = w1_rest + (size_t)(l - 1) * 4096;
                for (int idx = t; idx < 4096; idx += NT)
                    sm.g.w16[idx] = __float2half(w[idx]);
            }
            for (int i = t; i < 128; i += NT) sm.g.st[i] = 0.f;
            __syncthreads();

            if (b < ntile2) {
                int r0 = b << 7;
                int half = lane >> 4, c4 = lane & 15;
                float4 ca = *(const float4*)&sm.g.a[c4 * 4];
                float4 cb = *(const float4*)&sm.g.b[c4 * 4];
                const __half* hbase = g_h16 + pc + c4 * 4;

                // gather: 16 warps x 8 rows = 128 rows
                for (int rr = 0; rr < 8; rr++) {
                    int rl = warp * 8 + rr;
                    int row = r0 + rl;
                    float4 A = make_float4(0.f, 0.f, 0.f, 0.f);
                    auto accum = [&](uint2 raw) {
                        float2 f01 = __half22float2(*(__half2*)&raw.x);
                        float2 f23 = __half22float2(*(__half2*)&raw.y);
                        A.x += fmaxf(fmaf(f01.x, ca.x, cb.x), 0.f);
                        A.y += fmaxf(fmaf(f01.y, ca.y, cb.y), 0.f);
                        A.z += fmaxf(fmaf(f23.x, ca.z, cb.z), 0.f);
                        A.w += fmaxf(fmaf(f23.y, ca.w, cb.w), 0.f);
                    };
                    if (row < n) {
                        int beg = g_rowptr[row], end = g_rowptr[row + 1];
                        int j = beg + half;
                        while (j + 2 < end) {
                            int s0 = g_csrc[j];
                            int s1 = g_csrc[j + 2];
                            uint2 w0 = *(const uint2*)(hbase + (size_t)s0 * HL);
                            uint2 w1 = *(const uint2*)(hbase + (size_t)s1 * HL);
                            accum(w0);
                            accum(w1);
                            j += 4;
                        }
                        if (j < end) {
                            int s0 = g_csrc[j];
                            uint2 w0 = *(const uint2*)(hbase + (size_t)s0 * HL);
                            accum(w0);
                        }
                    }
                    A.x += __shfl_xor_sync(0xFFFFFFFFu, A.x, 16);
                    A.y += __shfl_xor_sync(0xFFFFFFFFu, A.y, 16);
                    A.z += __shfl_xor_sync(0xFFFFFFFFu, A.z, 16);
                    A.w += __shfl_xor_sync(0xFFFFFFFFu, A.w, 16);
                    if (half == 0) {
                        if (row < n) {
                            uint2 raw = *(const uint2*)(hbase + (size_t)row * HL);
                            accum(raw);
                        }
                        float* ip = &sm.g.in[rl][c4 * 4];
                        ip[0] = A.x; ip[1] = A.y; ip[2] = A.z; ip[3] = A.w;
                    }
                }
                __syncthreads();
                // GEMM: 2 rows x 8 cols per thread
                int r = t & 63, c0 = (t >> 6) * 8;
                float accA[8], accB[8];
                #pragma unroll
                for (int j = 0; j < 8; j++) { accA[j] = sm.g.bias[c0 + j]; accB[j] = accA[j]; }
                #pragma unroll
                for (int k = 0; k < 64; k++) {
                    float a0 = sm.g.in[r][k];
                    float a1 = sm.g.in[r + 64][k];
                    uint4 wr = *(const uint4*)&sm.g.w16[k * 64 + c0];
                    const __half2* wh = (const __half2*)&wr;
                    #pragma unroll
                    for (int m = 0; m < 4; m++) {
                        float2 f = __half22float2(wh[m]);
                        accA[2*m]   = fmaf(a0, f.x, accA[2*m]);
                        accA[2*m+1] = fmaf(a0, f.y, accA[2*m+1]);
                        accB[2*m]   = fmaf(a1, f.x, accB[2*m]);
                        accB[2*m+1] = fmaf(a1, f.y, accB[2*m+1]);
                    }
                }
                int gr0 = r0 + r, gr1 = r0 + r + 64;
                bool v0 = gr0 < n, v1 = gr1 < n;
                __syncthreads();           // all GEMM reads of in[] complete
                #pragma unroll
                for (int j = 0; j < 8; j++) {
                    sm.g.in[r][c0 + j]      = v0 ? accA[j] : 0.f;
                    sm.g.in[r + 64][c0 + j] = v1 ? accB[j] : 0.f;
                }
                #pragma unroll
                for (int j = 0; j < 8; j++) {
                    float s = (v0 ? accA[j] : 0.f) + (v1 ? accB[j] : 0.f);
                    float q = (v0 ? accA[j] * accA[j] : 0.f) + (v1 ? accB[j] * accB[j] : 0.f);
                    #pragma unroll
                    for (int o = 16; o > 0; o >>= 1) {
                        s += __shfl_down_sync(0xFFFFFFFFu, s, o);
                        q += __shfl_down_sync(0xFFFFFFFFu, q, o);
                    }
                    if (lane == 0) {
                        atomicAdd(&sm.g.st[c0 + j], s);
                        atomicAdd(&sm.g.st[64 + c0 + j], q);
                    }
                }
            }
            __syncthreads();
            if (t < 128) atomicAdd(&g_statp[slice + l * 256 + t], sm.g.st[t]);
            gbar();
        }

        // ===== gemm2: in-place BN on smem z, GEMM, h16 out =====
        {
            int zso = l * 256;
            if (t < 64) {
                float s1 = 0.f, s2 = 0.f;
                #pragma unroll 4
                for (int sl = 0; sl < NSLICE; sl++) {
                    const float* sp = g_statp + sl * STATSZ + zso;
                    s1 += __ldcg(sp + t);
                    s2 += __ldcg(sp + 64 + t);
                }
                float mean = s1 * invN;
                float var  = s2 * invN - mean * mean;
                float a = gm[l * HID + t] * rsqrtf(var + BN_EPS);
                sm.g.a[t] = a;
                sm.g.b[t] = bm[l * HID + t] - mean * a;
                sm.g.bias[t] = b2[l * HID + t];
            }
            {
                const float* w = w2 + (size_t)l * 4096;
                for (int idx = t; idx < 4096; idx += NT)
                    sm.g.w16[idx] = __float2half(w[idx]);
            }
            for (int i = t; i < 128; i += NT) sm.g.st[i] = 0.f;
            __syncthreads();

            if (b < ntile2) {
                int r0 = b << 7;
                // in-place relu(BN(z))
                for (int idx = t; idx < 8192; idx += NT) {
                    int r = idx >> 6, k = idx & 63;
                    float v = sm.g.in[r][k];
                    sm.g.in[r][k] = fmaxf(fmaf(v, sm.g.a[k], sm.g.b[k]), 0.f);
                }
                __syncthreads();
                int r = t & 63, c0 = (t >> 6) * 8;
                float accA[8], accB[8];
                #pragma unroll
                for (int j = 0; j < 8; j++) { accA[j] = sm.g.bias[c0 + j]; accB[j] = accA[j]; }
                #pragma unroll
                for (int k = 0; k < 64; k++) {
                    float a0 = sm.g.in[r][k];
                    float a1 = sm.g.in[r + 64][k];
                    uint4 wr = *(const uint4*)&sm.g.w16[k * 64 + c0];
                    const __half2* wh = (const __half2*)&wr;
                    #pragma unroll
                    for (int m = 0; m < 4; m++) {
                        float2 f = __half22float2(wh[m]);
                        accA[2*m]   = fmaf(a0, f.x, accA[2*m]);
                        accA[2*m+1] = fmaf(a0, f.y, accA[2*m+1]);
                        accB[2*m]   = fmaf(a1, f.x, accB[2*m]);
                        accB[2*m+1] = fmaf(a1, f.y, accB[2*m+1]);
                    }
                }
                int gr0 = r0 + r, gr1 = r0 + r + 64;
                bool v0 = gr0 < n, v1 = gr1 < n;
                if (v0) {
                    uint4 pk;
                    __half2* ph = (__half2*)&pk;
                    ph[0] = __float22half2_rn(make_float2(accA[0], accA[1]));
                    ph[1] = __float22half2_rn(make_float2(accA[2], accA[3]));
                    ph[2] = __float22half2_rn(make_float2(accA[4], accA[5]));
                    ph[3] = __float22half2_rn(make_float2(accA[6], accA[7]));
                    *(uint4*)(g_h16 + (size_t)gr0 * HL + l * HID + c0) = pk;
                }
                if (v1) {
                    uint4 pk;
                    __half2* ph = (__half2*)&pk;
                    ph[0] = __float22half2_rn(make_float2(accB[0], accB[1]));
                    ph[1] = __float22half2_rn(make_float2(accB[2], accB[3]));
                    ph[2] = __float22half2_rn(make_float2(accB[4], accB[5]));
                    ph[3] = __float22half2_rn(make_float2(accB[6], accB[7]));
                    *(uint4*)(g_h16 + (size_t)gr1 * HL + l * HID + c0) = pk;
                }
                #pragma unroll
                for (int j = 0; j < 8; j++) {
                    float s = (v0 ? accA[j] : 0.f) + (v1 ? accB[j] : 0.f);
                    float q = (v0 ? accA[j] * accA[j] : 0.f) + (v1 ? accB[j] * accB[j] : 0.f);
                    #pragma unroll
                    for (int o = 16; o > 0; o >>= 1) {
                        s += __shfl_down_sync(0xFFFFFFFFu, s, o);
                        q += __shfl_down_sync(0xFFFFFFFFu, q, o);
                    }
                    if (lane == 0) {
                        atomicAdd(&sm.g.st[c0 + j], s);
                        atomicAdd(&sm.g.st[64 + c0 + j], q);
                    }
                }
            }
            __syncthreads();
            if (t < 128) atomicAdd(&g_statp[slice + l * 256 + 128 + t], sm.g.st[t]);
            gbar();
        }
    }

    // ---------- pool + classifier ----------
    for (int c = t; c < HL; c += NT) {
        int l = c >> 6, ch = c & 63;
        int vso = l * 256 + 128;
        float s1 = 0.f, s2 = 0.f;
        for (int sl = 0; sl < NSLICE; sl++) {
            const float* sp = g_statp + sl * STATSZ + vso;
            s1 += __ldcg(sp + ch);
            s2 += __ldcg(sp + 64 + ch);
        }
        float mean = s1 * invN;
        float var  = s2 * invN - mean * mean;
        float a = go[c] * rsqrtf(var + BN_EPS);
        sm.p.a[c] = a;
        sm.p.b[c] = bo[c] - mean * a;
    }
    __syncthreads();
    {
        int is64 = g_is64_b;
        int warpsTotal = nb * 16;
        int gw = b * 16 + warp;
        for (int g = gw; g < GNUM; g += warpsTotal) {
            int se = n;
            if (lane < 2) {
                int key = g + lane;
                int lo = 0, hi = n;
                while (lo < hi) {
                    int mid = (lo + hi) >> 1;
                    if ((int)ldidx(batch, mid, is64) < key) lo = mid + 1;
                    else hi = mid;
                }
                se = lo;
            }
            int s0 = __shfl_sync(0xFFFFFFFFu, se, 0);
            int e0 = __shfl_sync(0xFFFFFFFFu, se, 1);
            float acc0[5], acc1[5];
            #pragma unroll
            for (int k = 0; k < 5; k++) { acc0[k] = 0.f; acc1[k] = 0.f; }
            float xsum = 0.f;
            int cbase = lane * 2;
            for (int r = s0; r < e0; r++) {
                xsum += x[r];
                const __half2* rp = (const __half2*)(g_h16 + (size_t)r * HL);
                #pragma unroll
                for (int k = 0; k < 5; k++) {
                    float2 f = __half22float2(rp[k * 32 + lane]);
                    int c = k * 64 + cbase;
                    acc0[k] += fmaxf(fmaf(f.x, sm.p.a[c], sm.p.b[c]), 0.f);
                    acc1[k] += fmaxf(fmaf(f.y, sm.p.a[c + 1], sm.p.b[c + 1]), 0.f);
                }
            }
            float o0 = 0.f, o1 = 0.f;
            #pragma unroll
            for (int k = 0; k < 5; k++) {
                int c = k * 64 + cbase;
                o0 = fmaf(acc0[k], lin_w[(1 + c) * 2 + 0], o0);
                o1 = fmaf(acc0[k], lin_w[(1 + c) * 2 + 1], o1);
                o0 = fmaf(acc1[k], lin_w[(2 + c) * 2 + 0], o0);
                o1 = fmaf(acc1[k], lin_w[(2 + c) * 2 + 1], o1);
            }
            #pragma unroll
            for (int o = 16; o > 0; o >>= 1) {
                o0 += __shfl_down_sync(0xFFFFFFFFu, o0, o);
                o1 += __shfl_down_sync(0xFFFFFFFFu, o1, o);
            }
            if (lane == 0) {
                out[g * 2 + 0] = o0 + xsum * lin_w[0] + lin_b[0];
                out[g * 2 + 1] = o1 + xsum * lin_w[1] + lin_b[1];
            }
        }
    }
}

// ---------------- launch ----------------
extern "C" void kernel_launch(void* const* d_in, const int* in_sizes, int n_in,
                              void* d_out, int out_size)
{
    const float* x      = (const float*)d_in[0];
    const void*  ei     = d_in[1];
    const void*  batch  = d_in[2];
    const float* w1_0   = (const float*)d_in[3];
    const float* w1_rest= (const float*)d_in[4];
    const float* b1     = (const float*)d_in[5];
    const float* gm     = (const float*)d_in[6];
    const float* bm     = (const float*)d_in[7];
    const float* w2     = (const float*)d_in[8];
    const float* b2     = (const float*)d_in[9];
    const float* go     = (const float*)d_in[10];
    const float* bo     = (const float*)d_in[11];
    const float* lin_w  = (const float*)d_in[12];
    const float* lin_b  = (const float*)d_in[13];
    float* out = (float*)d_out;

    int N = in_sizes[0];
    int E = in_sizes[1] / 2;
    float invN = 1.f / (float)N;

    fused_all<<<PB, NT>>>(x, ei, batch, w1_0, w1_rest, b1, gm, bm,
                          w2, b2, go, bo, lin_w, lin_b, out,
                          N, E, in_sizes[2], invN);
}

// round 17
// speedup vs baseline: 1.3805x; 1.1256x over previous
#include <cuda_runtime.h>
#include <cuda_fp16.h>
#include <cstdint>

#define NMAX 50000
#define EMAX 800000
#define GNUM 512
#define HID 64
#define LAY 5
#define HL 320
#define BN_EPS 1e-5f
#define PB 444
#define NT 512
#define NSLICE 16
#define STATSZ (LAY * 256)

typedef unsigned long long ull;

// ---------------- static scratch ----------------
__device__ __half g_h16[(size_t)NMAX * HL];     // RAW gemm2 outputs (pre-BN), fp16
__device__ float  g_statp[NSLICE * STATSZ];
__device__ int    g_deg[NMAX];
__device__ int    g_rowptr[NMAX + 1];
__device__ int    g_cur[NMAX];
__device__ int    g_part[256];
__device__ int    g_partscan[256];
__device__ int    g_csrc[EMAX + 8];
__device__ int    g_is64_e, g_is64_b;
__device__ unsigned g_count = 0, g_epoch = 0;

__device__ __forceinline__ long ldidx(const void* p, long i, int is64) {
    return is64 ? (long)((const long long*)p)[i] : (long)((const int*)p)[i];
}

__device__ __forceinline__ unsigned ld_epoch() {
    unsigned v;
    asm volatile("ld.global.cg.u32 %0, [%1];" : "=r"(v) : "l"(&g_epoch) : "memory");
    return v;
}

__device__ __forceinline__ void gbar() {
    __syncthreads();
    if (threadIdx.x == 0) {
        __threadfence();
        unsigned e = ld_epoch();
        if (atomicAdd(&g_count, 1) == gridDim.x - 1) {
            atomicExch(&g_count, 0u);
            __threadfence();
            atomicExch(&g_epoch, e + 1);
        } else {
            unsigned cur;
            do { __nanosleep(20); cur = ld_epoch(); } while (cur == e);
        }
        __threadfence();
    }
    __syncthreads();
}

// ---------------- f32x2 helpers ----------------
__device__ __forceinline__ ull pk2(float x, float y) {
    ull r;
    asm("mov.b64 %0, {%1, %2};" : "=l"(r) : "f"(x), "f"(y));
    return r;
}
__device__ __forceinline__ float2 upk(ull v) {
    float2 f;
    asm("mov.b64 {%0, %1}, %2;" : "=f"(f.x), "=f"(f.y) : "l"(v));
    return f;
}
__device__ __forceinline__ ull f2fma(ull a, ull b, ull c) {
    ull d;
    asm("fma.rn.f32x2 %0, %1, %2, %3;" : "=l"(d) : "l"(a), "l"(b), "l"(c));
    return d;
}

// ---------------- shared memory ----------------
#define IPITCH 66   // halfs per tile row (64 + 2 pad); 33 half2 -> conflict-free
struct SmGemm {
    float  w32[64 * 64];       // 16KB fp32 weights [k][c]
    __half inh[128 * IPITCH];  // 16.5KB fp16 tile: gather input / z
    float a[64];
    float b[64];
    float bias[64];
    float st[128];
    float xr[128];
};
struct SmPool { float a[HL]; float b[HL]; };
struct SmScan { int sh[NT + 1]; };
union __align__(16) SmU {
    SmGemm g; SmPool p; SmScan s;
};

__global__ void __launch_bounds__(NT, 3) fused_all(
    const float* __restrict__ x, const void* __restrict__ ei,
    const void* __restrict__ batch,
    const float* __restrict__ w1_0, const float* __restrict__ w1_rest,
    const float* __restrict__ b1,
    const float* __restrict__ gm, const float* __restrict__ bm,
    const float* __restrict__ w2, const float* __restrict__ b2,
    const float* __restrict__ go, const float* __restrict__ bo,
    const float* __restrict__ lin_w, const float* __restrict__ lin_b,
    float* __restrict__ out, int n, int E, int bcount, float invN)
{
    __shared__ SmU sm;
    int t = threadIdx.x, b = blockIdx.x, nb = gridDim.x;
    int lane = t & 31, warp = t >> 5;
    long gstride = (long)nb * NT;
    int slice = (b & (NSLICE - 1)) * STATSZ;

    // ---------- P0: zero + detect ----------
    for (long i = (long)b * NT + t; i < n; i += gstride) g_deg[i] = 0;
    for (long i = (long)b * NT + t; i < NSLICE * STATSZ; i += gstride) g_statp[i] = 0.f;
    if (b == 1) {
        const int* p = (const int*)ei;
        int f = 0;
        for (int i = t; i < 4096; i += NT) if (p[2 * i + 1] != 0) f = 1;
        f = __syncthreads_or(f);
        if (t == 0) g_is64_e = (f == 0);
        const int* q = (const int*)batch;
        int hf = bcount / 2;
        int f2 = 0;
        for (int i = t; i < 2048; i += NT) {
            int pos = hf - 1 - i;
            if (pos >= 0 && q[2 * pos + 1] != 0) f2 = 1;
        }
        f2 = __syncthreads_or(f2);
        if (t == 0) g_is64_b = (f2 == 0);
    }
    gbar();

    // ---------- P1: degree histogram ----------
    {
        int is64 = g_is64_e;
        for (long e0 = (long)b * NT + t; e0 < E; e0 += gstride) {
            int dst = (int)ldidx(ei, (long)E + e0, is64);
            atomicAdd(&g_deg[dst], 1);
        }
    }
    gbar();

    int nch = (n + NT - 1) / NT;

    // ---------- P2: chunk sums ----------
    for (int c = b; c < nch; c += nb) {
        int i = c * NT + t;
        sm.s.sh[t] = (i < n) ? g_deg[i] : 0;
        __syncthreads();
        for (int off = NT / 2; off > 0; off >>= 1) {
            if (t < off) sm.s.sh[t] += sm.s.sh[t + off];
            __syncthreads();
        }
        if (t == 0) g_part[c] = sm.s.sh[0];
        __syncthreads();
    }
    gbar();

    // ---------- P3: scan of chunk sums ----------
    if (b == 0) {
        int v = (t < nch) ? g_part[t] : 0;
        sm.s.sh[t] = v;
        __syncthreads();
        for (int off = 1; off < NT; off <<= 1) {
            int xv = (t >= off) ? sm.s.sh[t - off] : 0;
            __syncthreads();
            sm.s.sh[t] += xv;
            __syncthreads();
        }
        if (t < nch) g_partscan[t] = sm.s.sh[t] - v;
    }
    gbar();

    // ---------- P4: rowptr ----------
    for (int c = b; c < nch; c += nb) {
        int i = c * NT + t;
        int v = (i < n) ? g_deg[i] : 0;
        sm.s.sh[t] = v;
        __syncthreads();
        for (int off = 1; off < NT; off <<= 1) {
            int xv = (t >= off) ? sm.s.sh[t - off] : 0;
            __syncthreads();
            sm.s.sh[t] += xv;
            __syncthreads();
        }
        if (i < n) {
            int rp = g_partscan[c] + sm.s.sh[t] - v;
            g_rowptr[i] = rp;
            g_cur[i] = rp;
            if (i == n - 1) g_rowptr[n] = E;
        }
        __syncthreads();
    }
    gbar();

    // ---------- P5: fill CSR ----------
    {
        int is64 = g_is64_e;
        for (long e0 = (long)b * NT + t; e0 < E; e0 += gstride) {
            int src = (int)ldidx(ei, e0, is64);
            int dst = (int)ldidx(ei, (long)E + e0, is64);
            int pos = atomicAdd(&g_cur[dst], 1);
            g_csrc[pos] = src;
        }
    }
    gbar();

    int ntile2 = (n + 127) >> 7;   // 128-row tiles; ntile2 <= PB

    // ---------- P6: layer-0 (one 128-row tile per block, z -> smem fp16) ----------
    for (int i = t; i < 128; i += NT) sm.g.st[i] = 0.f;
    __syncthreads();
    if (b < ntile2) {
        int r0 = b << 7;
        for (int rr = 0; rr < 8; rr++) {
            int rl = warp * 8 + rr;
            int row = r0 + rl;
            float acc = 0.f;
            if (row < n) {
                int beg = g_rowptr[row], end = g_rowptr[row + 1];
                for (int j = beg + lane; j < end; j += 32)
                    acc += x[g_csrc[j]];
            }
            #pragma unroll
            for (int o = 16; o > 0; o >>= 1)
                acc += __shfl_xor_sync(0xFFFFFFFFu, acc, o);
            if (lane == 0)
                sm.g.xr[rl] = (row < n) ? (acc + x[row]) : 0.f;
        }
        __syncthreads();
        int c = t & 63, g4 = t >> 6;
        float wc = w1_0[c], bc = b1[c];
        float s = 0.f, q = 0.f;
        #pragma unroll
        for (int i = 0; i < 16; i++) {
            int rl = g4 * 16 + i;
            int row = r0 + rl;
            float zv = 0.f;
            if (row < n) {
                zv = sm.g.xr[rl] * wc + bc;
                s += zv; q += zv * zv;
            }
            sm.g.inh[rl * IPITCH + c] = __float2half(zv);
        }
        atomicAdd(&sm.g.st[c], s);
        atomicAdd(&sm.g.st[64 + c], q);
    }
    __syncthreads();
    if (t < 128) atomicAdd(&g_statp[slice + t], sm.g.st[t]);
    gbar();

    // ---------- layers ----------
    for (int l = 0; l < LAY; l++) {
        // ===== gemm1 + gather (l >= 1): z stays in smem (fp16) =====
        if (l > 0) {
            int pc = (l - 1) * HID;
            int pso = (l - 1) * 256 + 128;
            if (t < 64) {
                float s1 = 0.f, s2 = 0.f;
                #pragma unroll 4
                for (int sl = 0; sl < NSLICE; sl++) {
                    const float* sp = g_statp + sl * STATSZ + pso;
                    s1 += __ldcg(sp + t);
                    s2 += __ldcg(sp + 64 + t);
                }
                float mean = s1 * invN;
                float var  = s2 * invN - mean * mean;
                float a = go[pc + t] * rsqrtf(var + BN_EPS);
                sm.g.a[t] = a;
                sm.g.b[t] = bo[pc + t] - mean * a;
                sm.g.bias[t] = b1[l * HID + t];
            }
            {
                const float* w = w1_rest + (size_t)(l - 1) * 4096;
                for (int idx = t; idx < 4096; idx += NT)
                    sm.g.w32[idx] = w[idx];
            }
            for (int i = t; i < 128; i += NT) sm.g.st[i] = 0.f;
            __syncthreads();

            if (b < ntile2) {
                int r0 = b << 7;
                int half = lane >> 4, c4 = lane & 15;
                float4 ca = *(const float4*)&sm.g.a[c4 * 4];
                float4 cb = *(const float4*)&sm.g.b[c4 * 4];
                const __half* hbase = g_h16 + pc + c4 * 4;

                for (int rr = 0; rr < 8; rr++) {
                    int rl = warp * 8 + rr;
                    int row = r0 + rl;
                    float4 A = make_float4(0.f, 0.f, 0.f, 0.f);
                    auto accum = [&](uint2 raw) {
                        float2 f01 = __half22float2(*(__half2*)&raw.x);
                        float2 f23 = __half22float2(*(__half2*)&raw.y);
                        A.x += fmaxf(fmaf(f01.x, ca.x, cb.x), 0.f);
                        A.y += fmaxf(fmaf(f01.y, ca.y, cb.y), 0.f);
                        A.z += fmaxf(fmaf(f23.x, ca.z, cb.z), 0.f);
                        A.w += fmaxf(fmaf(f23.y, ca.w, cb.w), 0.f);
                    };
                    if (row < n) {
                        int beg = g_rowptr[row], end = g_rowptr[row + 1];
                        int j = beg + half;
                        while (j + 2 < end) {
                            int s0 = g_csrc[j];
                            int s1 = g_csrc[j + 2];
                            uint2 w0 = *(const uint2*)(hbase + (size_t)s0 * HL);
                            uint2 w1 = *(const uint2*)(hbase + (size_t)s1 * HL);
                            accum(w0);
                            accum(w1);
                            j += 4;
                        }
                        if (j < end) {
                            int s0 = g_csrc[j];
                            uint2 w0 = *(const uint2*)(hbase + (size_t)s0 * HL);
                            accum(w0);
                        }
                    }
                    A.x += __shfl_xor_sync(0xFFFFFFFFu, A.x, 16);
                    A.y += __shfl_xor_sync(0xFFFFFFFFu, A.y, 16);
                    A.z += __shfl_xor_sync(0xFFFFFFFFu, A.z, 16);
                    A.w += __shfl_xor_sync(0xFFFFFFFFu, A.w, 16);
                    if (half == 0) {
                        if (row < n) {
                            uint2 raw = *(const uint2*)(hbase + (size_t)row * HL);
                            accum(raw);
                        }
                        __half2* ip = (__half2*)(sm.g.inh + rl * IPITCH + c4 * 4);
                        ip[0] = __float22half2_rn(make_float2(A.x, A.y));
                        ip[1] = __float22half2_rn(make_float2(A.z, A.w));
                    }
                }
                __syncthreads();
                // GEMM: 2 rows x 8 cols per thread, f32x2
                int r = t & 63, c0 = (t >> 6) * 8;
                const __half2* i2 = (const __half2*)sm.g.inh;
                ull accA[4], accB[4];
                #pragma unroll
                for (int m = 0; m < 4; m++) {
                    ull bb = pk2(sm.g.bias[c0 + 2*m], sm.g.bias[c0 + 2*m + 1]);
                    accA[m] = bb; accB[m] = bb;
                }
                #pragma unroll
                for (int kp = 0; kp < 32; kp++) {
                    float2 fa0 = __half22float2(i2[r * 33 + kp]);
                    float2 fa1 = __half22float2(i2[(r + 64) * 33 + kp]);
                    {
                        int k = 2 * kp;
                        ulonglong2 w0 = *(const ulonglong2*)&sm.g.w32[k * 64 + c0];
                        ulonglong2 w1 = *(const ulonglong2*)&sm.g.w32[k * 64 + c0 + 4];
                        ull p0 = pk2(fa0.x, fa0.x), p1 = pk2(fa1.x, fa1.x);
                        accA[0] = f2fma(p0, w0.x, accA[0]);
                        accA[1] = f2fma(p0, w0.y, accA[1]);
                        accA[2] = f2fma(p0, w1.x, accA[2]);
                        accA[3] = f2fma(p0, w1.y, accA[3]);
                        accB[0] = f2fma(p1, w0.x, accB[0]);
                        accB[1] = f2fma(p1, w0.y, accB[1]);
                        accB[2] = f2fma(p1, w1.x, accB[2]);
                        accB[3] = f2fma(p1, w1.y, accB[3]);
                    }
                    {
                        int k = 2 * kp + 1;
                        ulonglong2 w0 = *(const ulonglong2*)&sm.g.w32[k * 64 + c0];
                        ulonglong2 w1 = *(const ulonglong2*)&sm.g.w32[k * 64 + c0 + 4];
                        ull p0 = pk2(fa0.y, fa0.y), p1 = pk2(fa1.y, fa1.y);
                        accA[0] = f2fma(p0, w0.x, accA[0]);
                        accA[1] = f2fma(p0, w0.y, accA[1]);
                        accA[2] = f2fma(p0, w1.x, accA[2]);
                        accA[3] = f2fma(p0, w1.y, accA[3]);
                        accB[0] = f2fma(p1, w0.x, accB[0]);
                        accB[1] = f2fma(p1, w0.y, accB[1]);
                        accB[2] = f2fma(p1, w1.x, accB[2]);
                        accB[3] = f2fma(p1, w1.y, accB[3]);
                    }
                }
                float vA[8], vB[8];
                #pragma unroll
                for (int m = 0; m < 4; m++) {
                    float2 fA = upk(accA[m]);
                    float2 fB = upk(accB[m]);
                    vA[2*m] = fA.x; vA[2*m+1] = fA.y;
                    vB[2*m] = fB.x; vB[2*m+1] = fB.y;
                }
                int gr0 = r0 + r, gr1 = r0 + r + 64;
                bool v0 = gr0 < n, v1 = gr1 < n;
                if (!v0) { vA[0]=vA[1]=vA[2]=vA[3]=vA[4]=vA[5]=vA[6]=vA[7]=0.f; }
                if (!v1) { vB[0]=vB[1]=vB[2]=vB[3]=vB[4]=vB[5]=vB[6]=vB[7]=0.f; }
                __syncthreads();           // all GEMM reads of tile complete
                {
                    __half2* i2w = (__half2*)sm.g.inh;
                    int kpb = c0 >> 1;
                    #pragma unroll
                    for (int m = 0; m < 4; m++) {
                        i2w[r * 33 + kpb + m]        = __float22half2_rn(make_float2(vA[2*m], vA[2*m+1]));
                        i2w[(r + 64) * 33 + kpb + m] = __float22half2_rn(make_float2(vB[2*m], vB[2*m+1]));
                    }
                }
                #pragma unroll
                for (int j = 0; j < 8; j++) {
                    float s = vA[j] + vB[j];
                    float q = vA[j] * vA[j] + vB[j] * vB[j];
                    #pragma unroll
                    for (int o = 16; o > 0; o >>= 1) {
                        s += __shfl_down_sync(0xFFFFFFFFu, s, o);
                        q += __shfl_down_sync(0xFFFFFFFFu, q, o);
                    }
                    if (lane == 0) {
                        atomicAdd(&sm.g.st[c0 + j], s);
                        atomicAdd(&sm.g.st[64 + c0 + j], q);
                    }
                }
            }
            __syncthreads();
            if (t < 128) atomicAdd(&g_statp[slice + l * 256 + t], sm.g.st[t]);
            gbar();
        }

        // ===== gemm2: in-place BN on smem z (fp16), f32x2 GEMM, h16 out =====
        {
            int zso = l * 256;
            if (t < 64) {
                float s1 = 0.f, s2 = 0.f;
                #pragma unroll 4
                for (int sl = 0; sl < NSLICE; sl++) {
                    const float* sp = g_statp + sl * STATSZ + zso;
                    s1 += __ldcg(sp + t);
                    s2 += __ldcg(sp + 64 + t);
                }
                float mean = s1 * invN;
                float var  = s2 * invN - mean * mean;
                float a = gm[l * HID + t] * rsqrtf(var + BN_EPS);
                sm.g.a[t] = a;
                sm.g.b[t] = bm[l * HID + t] - mean * a;
                sm.g.bias[t] = b2[l * HID + t];
            }
            {
                const float* w = w2 + (size_t)l * 4096;
                for (int idx = t; idx < 4096; idx += NT)
                    sm.g.w32[idx] = w[idx];
            }
            for (int i = t; i < 128; i += NT) sm.g.st[i] = 0.f;
            __syncthreads();

            if (b < ntile2) {
                int r0 = b << 7;
                __half2* i2w = (__half2*)sm.g.inh;
                // in-place relu(BN(z)) on half2
                for (int idx = t; idx < 4096; idx += NT) {
                    int rr = idx >> 5, kp = idx & 31;
                    float2 f = __half22float2(i2w[rr * 33 + kp]);
                    int c = kp * 2;
                    f.x = fmaxf(fmaf(f.x, sm.g.a[c],     sm.g.b[c]),     0.f);
                    f.y = fmaxf(fmaf(f.y, sm.g.a[c + 1], sm.g.b[c + 1]), 0.f);
                    i2w[rr * 33 + kp] = __float22half2_rn(f);
                }
                __syncthreads();
                int r = t & 63, c0 = (t >> 6) * 8;
                const __half2* i2 = (const __half2*)sm.g.inh;
                ull accA[4], accB[4];
                #pragma unroll
                for (int m = 0; m < 4; m++) {
                    ull bb = pk2(sm.g.bias[c0 + 2*m], sm.g.bias[c0 + 2*m + 1]);
                    accA[m] = bb; accB[m] = bb;
                }
                #pragma unroll
                for (int kp = 0; kp < 32; kp++) {
                    float2 fa0 = __half22float2(i2[r * 33 + kp]);
                    float2 fa1 = __half22float2(i2[(r + 64) * 33 + kp]);
                    {
                        int k = 2 * kp;
                        ulonglong2 w0 = *(const ulonglong2*)&sm.g.w32[k * 64 + c0];
                        ulonglong2 w1 = *(const ulonglong2*)&sm.g.w32[k * 64 + c0 + 4];
                        ull p0 = pk2(fa0.x, fa0.x), p1 = pk2(fa1.x, fa1.x);
                        accA[0] = f2fma(p0, w0.x, accA[0]);
                        accA[1] = f2fma(p0, w0.y, accA[1]);
                        accA[2] = f2fma(p0, w1.x, accA[2]);
                        accA[3] = f2fma(p0, w1.y, accA[3]);
                        accB[0] = f2fma(p1, w0.x, accB[0]);
                        accB[1] = f2fma(p1, w0.y, accB[1]);
                        accB[2] = f2fma(p1, w1.x, accB[2]);
                        accB[3] = f2fma(p1, w1.y, accB[3]);
                    }
                    {
                        int k = 2 * kp + 1;
                        ulonglong2 w0 = *(const ulonglong2*)&sm.g.w32[k * 64 + c0];
                        ulonglong2 w1 = *(const ulonglong2*)&sm.g.w32[k * 64 + c0 + 4];
                        ull p0 = pk2(fa0.y, fa0.y), p1 = pk2(fa1.y, fa1.y);
                        accA[0] = f2fma(p0, w0.x, accA[0]);
                        accA[1] = f2fma(p0, w0.y, accA[1]);
                        accA[2] = f2fma(p0, w1.x, accA[2]);
                        accA[3] = f2fma(p0, w1.y, accA[3]);
                        accB[0] = f2fma(p1, w0.x, accB[0]);
                        accB[1] = f2fma(p1, w0.y, accB[1]);
                        accB[2] = f2fma(p1, w1.x, accB[2]);
                        accB[3] = f2fma(p1, w1.y, accB[3]);
                    }
                }
                float vA[8], vB[8];
                #pragma unroll
                for (int m = 0; m < 4; m++) {
                    float2 fA = upk(accA[m]);
                    float2 fB = upk(accB[m]);
                    vA[2*m] = fA.x; vA[2*m+1] = fA.y;
                    vB[2*m] = fB.x; vB[2*m+1] = fB.y;
                }
                int gr0 = r0 + r, gr1 = r0 + r + 64;
                bool v0 = gr0 < n, v1 = gr1 < n;
                if (v0) {
                    uint4 pk;
                    __half2* ph = (__half2*)&pk;
                    ph[0] = __float22half2_rn(make_float2(vA[0], vA[1]));
                    ph[1] = __float22half2_rn(make_float2(vA[2], vA[3]));
                    ph[2] = __float22half2_rn(make_float2(vA[4], vA[5]));
                    ph[3] = __float22half2_rn(make_float2(vA[6], vA[7]));
                    *(uint4*)(g_h16 + (size_t)gr0 * HL + l * HID + c0) = pk;
                }
                if (v1) {
                    uint4 pk;
                    __half2* ph = (__half2*)&pk;
                    ph[0] = __float22half2_rn(make_float2(vB[0], vB[1]));
                    ph[1] = __float22half2_rn(make_float2(vB[2], vB[3]));
                    ph[2] = __float22half2_rn(make_float2(vB[4], vB[5]));
                    ph[3] = __float22half2_rn(make_float2(vB[6], vB[7]));
                    *(uint4*)(g_h16 + (size_t)gr1 * HL + l * HID + c0) = pk;
                }
                #pragma unroll
                for (int j = 0; j < 8; j++) {
                    float s = (v0 ? vA[j] : 0.f) + (v1 ? vB[j] : 0.f);
                    float q = (v0 ? vA[j] * vA[j] : 0.f) + (v1 ? vB[j] * vB[j] : 0.f);
                    #pragma unroll
                    for (int o = 16; o > 0; o >>= 1) {
                        s += __shfl_down_sync(0xFFFFFFFFu, s, o);
                        q += __shfl_down_sync(0xFFFFFFFFu, q, o);
                    }
                    if (lane == 0) {
                        atomicAdd(&sm.g.st[c0 + j], s);
                        atomicAdd(&sm.g.st[64 + c0 + j], q);
                    }
                }
            }
            __syncthreads();
            if (t < 128) atomicAdd(&g_statp[slice + l * 256 + 128 + t], sm.g.st[t]);
            gbar();
        }
    }

    // ---------- pool + classifier ----------
    for (int c = t; c < HL; c += NT) {
        int l = c >> 6, ch = c & 63;
        int vso = l * 256 + 128;
        float s1 = 0.f, s2 = 0.f;
        for (int sl = 0; sl < NSLICE; sl++) {
            const float* sp = g_statp + sl * STATSZ + vso;
            s1 += __ldcg(sp + ch);
            s2 += __ldcg(sp + 64 + ch);
        }
        float mean = s1 * invN;
        float var  = s2 * invN - mean * mean;
        float a = go[c] * rsqrtf(var + BN_EPS);
        sm.p.a[c] = a;
        sm.p.b[c] = bo[c] - mean * a;
    }
    __syncthreads();
    {
        int is64 = g_is64_b;
        int warpsTotal = nb * 16;
        int gw = b * 16 + warp;
        for (int g = gw; g < GNUM; g += warpsTotal) {
            int se = n;
            if (lane < 2) {
                int key = g + lane;
                int lo = 0, hi = n;
                while (lo < hi) {
                    int mid = (lo + hi) >> 1;
                    if ((int)ldidx(batch, mid, is64) < key) lo = mid + 1;
                    else hi = mid;
                }
                se = lo;
            }
            int s0 = __shfl_sync(0xFFFFFFFFu, se, 0);
            int e0 = __shfl_sync(0xFFFFFFFFu, se, 1);
            float acc0[5], acc1[5];
            #pragma unroll
            for (int k = 0; k < 5; k++) { acc0[k] = 0.f; acc1[k] = 0.f; }
            float xsum = 0.f;
            int cbase = lane * 2;
            for (int r = s0; r < e0; r++) {
                xsum += x[r];
                const __half2* rp = (const __half2*)(g_h16 + (size_t)r * HL);
                #pragma unroll
                for (int k = 0; k < 5; k++) {
                    float2 f = __half22float2(rp[k * 32 + lane]);
                    int c = k * 64 + cbase;
                    acc0[k] += fmaxf(fmaf(f.x, sm.p.a[c], sm.p.b[c]), 0.f);
                    acc1[k] += fmaxf(fmaf(f.y, sm.p.a[c + 1], sm.p.b[c + 1]), 0.f);
                }
            }
            float o0 = 0.f, o1 = 0.f;
            #pragma unroll
            for (int k = 0; k < 5; k++) {
                int c = k * 64 + cbase;
                o0 = fmaf(acc0[k], lin_w[(1 + c) * 2 + 0], o0);
                o1 = fmaf(acc0[k], lin_w[(1 + c) * 2 + 1], o1);
                o0 = fmaf(acc1[k], lin_w[(2 + c) * 2 + 0], o0);
                o1 = fmaf(acc1[k], lin_w[(2 + c) * 2 + 1], o1);
            }
            #pragma unroll
            for (int o = 16; o > 0; o >>= 1) {
                o0 += __shfl_down_sync(0xFFFFFFFFu, o0, o);
                o1 += __shfl_down_sync(0xFFFFFFFFu, o1, o);
            }
            if (lane == 0) {
                out[g * 2 + 0] = o0 + xsum * lin_w[0] + lin_b[0];
                out[g * 2 + 1] = o1 + xsum * lin_w[1] + lin_b[1];
            }
        }
    }
}

// ---------------- launch ----------------
extern "C" void kernel_launch(void* const* d_in, const int* in_sizes, int n_in,
                              void* d_out, int out_size)
{
    const float* x      = (const float*)d_in[0];
    const void*  ei     = d_in[1];
    const void*  batch  = d_in[2];
    const float* w1_0   = (const float*)d_in[3];
    const float* w1_rest= (const float*)d_in[4];
    const float* b1     = (const float*)d_in[5];
    const float* gm     = (const float*)d_in[6];
    const float* bm     = (const float*)d_in[7];
    const float* w2     = (const float*)d_in[8];
    const float* b2     = (const float*)d_in[9];
    const float* go     = (const float*)d_in[10];
    const float* bo     = (const float*)d_in[11];
    const float* lin_w  = (const float*)d_in[12];
    const float* lin_b  = (const float*)d_in[13];
    float* out = (float*)d_out;

    int N = in_sizes[0];
    int E = in_sizes[1] / 2;
    float invN = 1.f / (float)N;

    fused_all<<<PB, NT>>>(x, ei, batch, w1_0, w1_rest, b1, gm, bm,
                          w2, b2, go, bo, lin_w, lin_b, out,
                          N, E, in_sizes[2], invN);
}